// round 14
// baseline (speedup 1.0000x reference)
#include <cuda_runtime.h>
#include <cuda_bf16.h>
#include <math.h>
#include <float.h>
#include <stdint.h>

// Problem constants
#define Bc    2
#define Sc    1024
#define HIDc  2048
#define NHc   16
#define HDc   128
#define SBc   20
#define RBc   82
#define CBc   163
#define FFc   0.9f
#define BSc   (Bc*Sc)          // 2048
#define ZB    (Bc*NHc)         // 32
#define NELT  (BSc*HIDc)       // 4M
#define HEADROWS (CBc+1)       // 164 rows with no evict dependency
#define TAILROWS (Sc-HEADROWS) // 860

// ----------------------------------------------------------------------------
// Scratch
// ----------------------------------------------------------------------------
__device__ __align__(1024) float g_lin[3*NELT];
__device__ __align__(1024) __nv_bfloat16 g_hsH[NELT];
__device__ __align__(1024) __nv_bfloat16 g_hsL[NELT];
__device__ __align__(1024) __nv_bfloat16 g_wH[4*HIDc*HIDc];
__device__ __align__(1024) __nv_bfloat16 g_wL[4*HIDc*HIDc];
__device__ __align__(1024) __nv_bfloat16 g_QH[ZB*Sc*HDc];
__device__ __align__(1024) __nv_bfloat16 g_QL[ZB*Sc*HDc];
__device__ __align__(1024) __nv_bfloat16 g_KH[ZB*Sc*HDc];
__device__ __align__(1024) __nv_bfloat16 g_KL[ZB*Sc*HDc];
__device__ __align__(1024) __nv_bfloat16 g_VH[ZB*Sc*HDc];
__device__ __align__(1024) __nv_bfloat16 g_VL[ZB*Sc*HDc];
__device__ __align__(1024) float g_P[(size_t)ZB*Sc*Sc];
__device__ __align__(1024) __nv_bfloat16 g_PH[(size_t)ZB*Sc*Sc];
__device__ __align__(1024) __nv_bfloat16 g_PL[(size_t)ZB*Sc*Sc];
__device__ __align__(1024) __nv_bfloat16 g_cH[NELT];
__device__ __align__(1024) __nv_bfloat16 g_cL[NELT];
__device__ int g_evict[ZB*Sc];
__device__ volatile int g_prog[ZB];
__device__ float g_tcos[Sc*64];
__device__ float g_tsin[Sc*64];
__device__ float g_wcoef[CBc];

// ----------------------------------------------------------------------------
// PTX helpers
// ----------------------------------------------------------------------------
__device__ __forceinline__ uint32_t smem_u32(const void* p){
    uint32_t a;
    asm("{ .reg .u64 t; cvta.to.shared.u64 t, %1; cvt.u32.u64 %0, t; }":"=r"(a):"l"(p));
    return a;
}
__device__ __forceinline__ void cp16(uint32_t d, const void* s){
    asm volatile("cp.async.cg.shared.global [%0], [%1], 16;"::"r"(d),"l"(s));
}
#define CP_COMMIT() asm volatile("cp.async.commit_group;":::"memory")
#define CP_WAIT(n)  asm volatile("cp.async.wait_group %0;"::"n"(n):"memory")

__device__ __forceinline__ void ldsm4(uint32_t r[4], uint32_t a){
    asm volatile("ldmatrix.sync.aligned.m8n8.x4.shared.b16 {%0,%1,%2,%3}, [%4];"
        : "=r"(r[0]),"=r"(r[1]),"=r"(r[2]),"=r"(r[3]) : "r"(a));
}
__device__ __forceinline__ void ldsm4t(uint32_t r[4], uint32_t a){
    asm volatile("ldmatrix.sync.aligned.m8n8.x4.trans.shared.b16 {%0,%1,%2,%3}, [%4];"
        : "=r"(r[0]),"=r"(r[1]),"=r"(r[2]),"=r"(r[3]) : "r"(a));
}
__device__ __forceinline__ void mma16816(float d[4], const uint32_t a[4], const uint32_t b[2]){
    asm volatile("mma.sync.aligned.m16n8k16.row.col.f32.bf16.bf16.f32 "
        "{%0,%1,%2,%3},{%4,%5,%6,%7},{%8,%9},{%0,%1,%2,%3};"
        : "+f"(d[0]),"+f"(d[1]),"+f"(d[2]),"+f"(d[3])
        : "r"(a[0]),"r"(a[1]),"r"(a[2]),"r"(a[3]),"r"(b[0]),"r"(b[1]));
}

#define GSMEM_TOTAL 196608   // 192 KB

template<int NROWS, int NTH>
__device__ __forceinline__ void copy_rk(uint32_t dst, const __nv_bfloat16* src,
                                        int ld, int tid){
#pragma unroll
    for (int i=0;i<NROWS*8/NTH;i++){
        int idx = tid + i*NTH;
        int r = idx>>3, c = idx&7;
        uint32_t sw = (uint32_t)(r*128) + (uint32_t)(((c ^ (r&7))<<4));
        cp16(dst + sw, (const char*)src + ((long long)r*ld + c*8)*2);
    }
}
template<int NCOLS, int NTH>
__device__ __forceinline__ void copy_kn(uint32_t dst, const __nv_bfloat16* src,
                                        int ld, int tid){
    const int CPR = NCOLS/8;
#pragma unroll
    for (int i=0;i<64*CPR/NTH;i++){
        int idx = tid + i*NTH;
        int r = idx/CPR, c = idx%CPR;
        uint32_t sw = (uint32_t)(r*(NCOLS*2)) + (uint32_t)(((c ^ (r&7))<<4));
        cp16(dst + sw, (const char*)src + ((long long)r*ld + c*8)*2);
    }
}

// ----------------------------------------------------------------------------
// HMMA GEMM (R9-proven)
// ----------------------------------------------------------------------------
template<int NTH, int NT, bool BKN, bool CAUSAL, bool SPLITOUT, bool KTRUNC>
__global__ void __launch_bounds__(NTH) gemm_mma(
    const __nv_bfloat16* __restrict__ Ah, const __nv_bfloat16* __restrict__ Al,
    const __nv_bfloat16* __restrict__ Bh, const __nv_bfloat16* __restrict__ Bl,
    float* __restrict__ C,
    __nv_bfloat16* __restrict__ CH, __nv_bfloat16* __restrict__ CL,
    int K, int ldb, int ldc,
    long long sA, long long sB, long long sCo, long long sCi, int ndiv, float alpha)
{
    const int my = KTRUNC ? (gridDim.y - 1 - blockIdx.y) : blockIdx.y;
    const int m0 = my*128, n0 = blockIdx.x*NT, z = blockIdx.z;
    if (CAUSAL && n0 > m0 + 127) return;
    const int NN8 = NT/32;
    const int NHALF = NN8/4;
    const int MWT = (NTH==512) ? 32 : 64;
    const int MB  = MWT/16;
    const int TILEA = 16384;
    const int TILEBB = NT*128;
    const int STG = 2*TILEA + 2*TILEBB;
    const int NS = (NT==256) ? 2 : 3;

    extern __shared__ __align__(1024) char smem[];
    const uint32_t sb = smem_u32(smem);
    Ah += (long long)z*sA; Al += (long long)z*sA;
    Bh += (long long)z*sB; Bl += (long long)z*sB;
    long long coff = (long long)(z/ndiv)*sCo + (long long)(z%ndiv)*sCi;
    if (SPLITOUT){ CH += coff; CL += coff; } else { C += coff; }

    const int tid = threadIdx.x, lane = tid&31, wid = tid>>5;
    const int wm = wid>>2, wn = wid&3;

    float acc[MB][NN8][4];
#pragma unroll
    for (int a=0;a<MB;a++)
#pragma unroll
        for (int b=0;b<NN8;b++)
#pragma unroll
            for (int c=0;c<4;c++) acc[a][b][c] = 0.f;

    const int nch = KTRUNC ? ((m0+128)>>6) : (K>>6);

#define LOAD_CHUNK(cc, ss) do{ \
    uint32_t bbase = sb + (uint32_t)(ss)*STG; \
    copy_rk<128,NTH>(bbase,         Ah + (long long)m0*K + (cc)*64, K, tid); \
    copy_rk<128,NTH>(bbase + TILEA, Al + (long long)m0*K + (cc)*64, K, tid); \
    if (BKN){ \
        copy_kn<NT,NTH>(bbase + 2*TILEA,          Bh + (long long)(cc)*64*ldb + n0, ldb, tid); \
        copy_kn<NT,NTH>(bbase + 2*TILEA + TILEBB, Bl + (long long)(cc)*64*ldb + n0, ldb, tid); \
    } else { \
        copy_rk<NT,NTH>(bbase + 2*TILEA,          Bh + (long long)n0*K + (cc)*64, K, tid); \
        copy_rk<NT,NTH>(bbase + 2*TILEA + TILEBB, Bl + (long long)n0*K + (cc)*64, K, tid); \
    } \
    CP_COMMIT(); }while(0)

    LOAD_CHUNK(0, 0);
    if (NS > 1 && nch > 1) LOAD_CHUNK(1, 1);
    if (NS > 2 && nch > 2) LOAD_CHUNK(2, 2);

    const uint32_t axor = (uint32_t)(lane&7);

    for (int c=0; c<nch; c++){
        int pend = nch-1-c; if (pend > NS-1) pend = NS-1;
        if (pend >= 2) CP_WAIT(2);
        else if (pend == 1) CP_WAIT(1);
        else CP_WAIT(0);
        __syncthreads();
        uint32_t base = sb + (uint32_t)(c % NS)*STG;
#pragma unroll
        for (int ks=0; ks<4; ks++){
#pragma unroll
            for (int half=0; half<NHALF; half++){
                uint32_t bh[4][2], bl[4][2];
#pragma unroll
                for (int nb=0;nb<2;nb++){
                    uint32_t t[4];
                    int gg = half*2 + nb;
                    if (BKN){
                        uint32_t row = (uint32_t)(ks*16 + (lane&7) + (((lane>>3)&1)<<3));
                        uint32_t ch  = ((uint32_t)(wn*NN8 + gg*2 + (lane>>4)) ^ axor);
                        uint32_t ad  = base + 2*TILEA + row*(NT*2) + (ch<<4);
                        ldsm4t(t, ad);
                        bh[2*nb][0]=t[0]; bh[2*nb][1]=t[1]; bh[2*nb+1][0]=t[2]; bh[2*nb+1][1]=t[3];
                        ldsm4t(t, ad + TILEBB);
                        bl[2*nb][0]=t[0]; bl[2*nb][1]=t[1]; bl[2*nb+1][0]=t[2]; bl[2*nb+1][1]=t[3];
                    } else {
                        uint32_t row = (uint32_t)(wn*(NT/4) + gg*16 + (lane&7) + ((lane>>4)<<3));
                        uint32_t ch  = ((uint32_t)(ks*2 + ((lane>>3)&1)) ^ axor);
                        uint32_t ad  = base + 2*TILEA + row*128 + (ch<<4);
                        ldsm4(t, ad);
                        bh[2*nb][0]=t[0]; bh[2*nb][1]=t[1]; bh[2*nb+1][0]=t[2]; bh[2*nb+1][1]=t[3];
                        ldsm4(t, ad + TILEBB);
                        bl[2*nb][0]=t[0]; bl[2*nb][1]=t[1]; bl[2*nb+1][0]=t[2]; bl[2*nb+1][1]=t[3];
                    }
                }
#pragma unroll
                for (int mb=0;mb<MB;mb++){
                    uint32_t ah[4], al[4];
                    uint32_t row = (uint32_t)(wm*MWT + mb*16 + (lane&15));
                    uint32_t col = (((uint32_t)(ks*2 + (lane>>4)) ^ (row&7u))<<4);
                    uint32_t ad = base + row*128 + col;
                    ldsm4(ah, ad);
                    ldsm4(al, ad + TILEA);
#pragma unroll
                    for (int n8=0;n8<4;n8++){
                        int g8 = half*4 + n8;
                        mma16816(acc[mb][g8], ah, bh[n8]);
                        mma16816(acc[mb][g8], ah, bl[n8]);
                        mma16816(acc[mb][g8], al, bh[n8]);
                    }
                }
            }
        }
        __syncthreads();
        if (c + NS < nch) LOAD_CHUNK(c + NS, c % NS);
    }
#undef LOAD_CHUNK

#pragma unroll
    for (int mb=0;mb<MB;mb++){
        int r0 = m0 + wm*MWT + mb*16 + (lane>>2);
#pragma unroll
        for (int n8=0;n8<NN8;n8++){
            int cc = n0 + wn*(NT/4) + n8*8 + (lane&3)*2;
            float vx0 = acc[mb][n8][0]*alpha, vy0 = acc[mb][n8][1]*alpha;
            float vx1 = acc[mb][n8][2]*alpha, vy1 = acc[mb][n8][3]*alpha;
            if (SPLITOUT){
                __nv_bfloat162 h0, l0, h1, l1;
                h0.x = __float2bfloat16(vx0); h0.y = __float2bfloat16(vy0);
                l0.x = __float2bfloat16(vx0 - __bfloat162float(h0.x));
                l0.y = __float2bfloat16(vy0 - __bfloat162float(h0.y));
                h1.x = __float2bfloat16(vx1); h1.y = __float2bfloat16(vy1);
                l1.x = __float2bfloat16(vx1 - __bfloat162float(h1.x));
                l1.y = __float2bfloat16(vy1 - __bfloat162float(h1.y));
                *(__nv_bfloat162*)&CH[(long long)r0*ldc + cc] = h0;
                *(__nv_bfloat162*)&CL[(long long)r0*ldc + cc] = l0;
                *(__nv_bfloat162*)&CH[(long long)(r0+8)*ldc + cc] = h1;
                *(__nv_bfloat162*)&CL[(long long)(r0+8)*ldc + cc] = l1;
            } else {
                float2 v0; v0.x = vx0; v0.y = vy0;
                float2 v1; v1.x = vx1; v1.y = vy1;
                *(float2*)&C[(long long)r0*ldc + cc] = v0;
                *(float2*)&C[(long long)(r0+8)*ldc + cc] = v1;
            }
        }
    }
}

// ----------------------------------------------------------------------------
// fp32 -> bf16 hi/lo split; 8 elems/thread
// ----------------------------------------------------------------------------
__device__ __forceinline__ void split_body(const float* __restrict__ X,
                                           __nv_bfloat16* __restrict__ H,
                                           __nv_bfloat16* __restrict__ L, int i)
{
    float4 v = *(const float4*)&X[i];
    float4 w = *(const float4*)&X[i+4];
    __nv_bfloat16 h0=__float2bfloat16(v.x), h1=__float2bfloat16(v.y);
    __nv_bfloat16 h2=__float2bfloat16(v.z), h3=__float2bfloat16(v.w);
    __nv_bfloat16 h4=__float2bfloat16(w.x), h5=__float2bfloat16(w.y);
    __nv_bfloat16 h6=__float2bfloat16(w.z), h7=__float2bfloat16(w.w);
    __nv_bfloat162 H01{h0,h1}, H23{h2,h3}, H45{h4,h5}, H67{h6,h7};
    *(__nv_bfloat162*)&H[i]   = H01; *(__nv_bfloat162*)&H[i+2] = H23;
    *(__nv_bfloat162*)&H[i+4] = H45; *(__nv_bfloat162*)&H[i+6] = H67;
    __nv_bfloat162 L01, L23, L45, L67;
    L01.x = __float2bfloat16(v.x - __bfloat162float(h0));
    L01.y = __float2bfloat16(v.y - __bfloat162float(h1));
    L23.x = __float2bfloat16(v.z - __bfloat162float(h2));
    L23.y = __float2bfloat16(v.w - __bfloat162float(h3));
    L45.x = __float2bfloat16(w.x - __bfloat162float(h4));
    L45.y = __float2bfloat16(w.y - __bfloat162float(h5));
    L67.x = __float2bfloat16(w.z - __bfloat162float(h6));
    L67.y = __float2bfloat16(w.w - __bfloat162float(h7));
    *(__nv_bfloat162*)&L[i]   = L01; *(__nv_bfloat162*)&L[i+2] = L23;
    *(__nv_bfloat162*)&L[i+4] = L45; *(__nv_bfloat162*)&L[i+6] = L67;
}

__global__ void split_plain(const float* __restrict__ X,
                            __nv_bfloat16* __restrict__ H,
                            __nv_bfloat16* __restrict__ L, int n)
{
    int i = (blockIdx.x*blockDim.x + threadIdx.x)*8;
    if (i < n) split_body(X, H, L, i);
}

__global__ void split_w4(const float* __restrict__ w0, const float* __restrict__ w1,
                         const float* __restrict__ w2, const float* __restrict__ w3,
                         __nv_bfloat16* __restrict__ H, __nv_bfloat16* __restrict__ L)
{
    const float* src = (blockIdx.y==0)?w0:(blockIdx.y==1)?w1:(blockIdx.y==2)?w2:w3;
    size_t off = (size_t)blockIdx.y * HIDc * HIDc;
    int i = (blockIdx.x*blockDim.x + threadIdx.x)*8;
    split_body(src, H + off, L + off, i);
}

// ----------------------------------------------------------------------------
// Tables + evict/progress init
// ----------------------------------------------------------------------------
__global__ void rope_tables()
{
    int idx = blockIdx.x*blockDim.x + threadIdx.x;
    int s = idx >> 6, i = idx & 63;
    double inv = pow(10000.0, -(double)i/64.0);
    double a = (double)s * inv;
    g_tcos[idx] = (float)cos(a);
    g_tsin[idx] = (float)sin(a);
    if (idx < CBc) g_wcoef[idx] = (float)pow((double)FFc, (double)(CBc-1-idx));
    if (idx < ZB*Sc) g_evict[idx] = 0x7fffffff;
    if (idx < ZB) g_prog[idx] = 0;
}

// ----------------------------------------------------------------------------
// RoPE + layout + split
// ----------------------------------------------------------------------------
__global__ void rope_split()
{
    long long idx = (long long)blockIdx.x * blockDim.x + threadIdx.x;
    if (idx >= (long long)NELT) return;

    int d = (int)(idx % HDc);
    int h = (int)((idx / HDc) % NHc);
    int s = (int)((idx / HIDc) % Sc);
    int b = (int)(idx / ((long long)Sc * HIDc));
    int z = b*NHc + h;

    long long lin = (long long)(b * Sc + s) * HIDc + h * HDc + d;
    long long out = (long long)(z * Sc + s) * HDc + d;

    const float* Qlin = g_lin;
    const float* Klin = g_lin + NELT;
    const float* Vlin = g_lin + 2*(long long)NELT;

    float q = Qlin[lin];
    float k = Klin[lin];
    float qr, kr;
    if (d < 64) { qr = -Qlin[lin + 64]; kr = -Klin[lin + 64]; }
    else        { qr =  Qlin[lin - 64]; kr =  Klin[lin - 64]; }

    int ti = (s<<6) + (d & 63);
    float c = g_tcos[ti], sn = g_tsin[ti];

    float qv = q * c + qr * sn;
    float kv = k * c + kr * sn;

    __nv_bfloat16 qh = __float2bfloat16(qv);
    g_QH[out] = qh; g_QL[out] = __float2bfloat16(qv - __bfloat162float(qh));
    __nv_bfloat16 kh = __float2bfloat16(kv);
    g_KH[out] = kh; g_KL[out] = __float2bfloat16(kv - __bfloat162float(kh));

    float vv = Vlin[lin];
    __nv_bfloat16 vh = __float2bfloat16(vv);
    g_VH[out] = vh; g_VL[out] = __float2bfloat16(vv - __bfloat162float(vh));
}

// ----------------------------------------------------------------------------
// Causal row softmax (R9)
// ----------------------------------------------------------------------------
__global__ void __launch_bounds__(256) softmax_causal(float* __restrict__ P)
{
    __shared__ float smA[9];
    __shared__ float smB[9];
    long long row = blockIdx.x;
    int r = (int)(row & (Sc-1));
    float* p = P + row * Sc;
    const int tid = threadIdx.x;
    const int lane = tid & 31, wid = tid >> 5;

    float v[4];
    float mx = -FLT_MAX;
#pragma unroll
    for (int i = 0; i < 4; i++) {
        int jj = tid + i*256;
        v[i] = (jj <= r) ? p[jj] : -FLT_MAX;
        mx = fmaxf(mx, v[i]);
    }
#pragma unroll
    for (int o = 16; o; o >>= 1) mx = fmaxf(mx, __shfl_xor_sync(0xffffffffu, mx, o));
    if (lane == 0) smA[wid] = mx;
    __syncthreads();
    if (tid < 8) {
        float x = smA[tid];
#pragma unroll
        for (int o = 4; o; o >>= 1) x = fmaxf(x, __shfl_xor_sync(0xffu, x, o));
        if (tid == 0) smA[8] = x;
    }
    __syncthreads();
    mx = smA[8];

    float sum = 0.f;
#pragma unroll
    for (int i = 0; i < 4; i++) { v[i] = expf(v[i] - mx); sum += v[i]; }
#pragma unroll
    for (int o = 16; o; o >>= 1) sum += __shfl_xor_sync(0xffffffffu, sum, o);
    if (lane == 0) smB[wid] = sum;
    __syncthreads();
    if (tid < 8) {
        float x = smB[tid];
#pragma unroll
        for (int o = 4; o; o >>= 1) x += __shfl_xor_sync(0xffu, x, o);
        if (tid == 0) smB[8] = x;
    }
    __syncthreads();
    sum = smB[8];

    float inv = 1.f / sum;
#pragma unroll
    for (int i = 0; i < 4; i++) p[tid + i * 256] = v[i] * inv;
}

// ----------------------------------------------------------------------------
// FAT kernel:
//  blocks [0,ZB)                      : eviction scan (publishes progress)
//  blocks [ZB, ZB+ZB*HEADROWS)        : head maskrenorm (no dependency)
//  blocks >= ZB+ZB*HEADROWS           : tail maskrenorm, spin on progress
// Tail row r needs only evictions with t < r: evict[] transitions
// INT_MAX -> t, and both satisfy (e[j] >= r) identically when t >= r.
// ----------------------------------------------------------------------------
__global__ void __launch_bounds__(128) scan_fat(const float* __restrict__ P,
                                               int* __restrict__ evict,
                                               __nv_bfloat16* __restrict__ PH,
                                               __nv_bfloat16* __restrict__ PL)
{
    const int tid = threadIdx.x;
    const int lane = tid & 31, wid = tid >> 5;

    if (blockIdx.x >= ZB){
        __shared__ float hs[4];
        int bi = blockIdx.x - ZB;
        int z, r;
        bool tail = (bi >= ZB*HEADROWS);
        if (!tail){ z = bi / HEADROWS; r = bi % HEADROWS; }
        else {
            int ti2 = bi - ZB*HEADROWS;         // r-ascending ordering
            r = HEADROWS + (ti2 >> 5);          // ti2 / ZB
            z = ti2 & 31;                       // ti2 % ZB
        }
        long long row = (long long)z * Sc + r;
        const float* p = P + row * Sc;
        const int* e = evict + z * Sc;
        int j0 = tid * 8;

        if (tail){
            // wait until scan progress covers evictions with t <= r-1
            if (tid == 0){
                while (g_prog[z] < r - 1) __nanosleep(128);
            }
            __syncthreads();
            __threadfence();                     // acquire
        }

        float v[8];
        float4 a = *(const float4*)&p[j0];
        float4 b = *(const float4*)&p[j0+4];
        v[0]=a.x;v[1]=a.y;v[2]=a.z;v[3]=a.w;v[4]=b.x;v[5]=b.y;v[6]=b.z;v[7]=b.w;
        if (tail){
#pragma unroll
            for (int k=0;k<8;k++)
                if (e[j0+k] < r) v[k] = 0.f;
        }
        float sum = 0.f;
#pragma unroll
        for (int k=0;k<8;k++) sum += v[k];
#pragma unroll
        for (int o=16;o;o>>=1) sum += __shfl_xor_sync(0xffffffffu, sum, o);
        if (lane == 0) hs[wid] = sum;
        __syncthreads();
        float total = hs[0]+hs[1]+hs[2]+hs[3];
        float inv = 1.f / total;
        long long base = row * Sc;
        __nv_bfloat162 H[4], L[4];
#pragma unroll
        for (int k=0;k<4;k++){
            float x = v[2*k]*inv, y = v[2*k+1]*inv;
            H[k].x = __float2bfloat16(x); H[k].y = __float2bfloat16(y);
            L[k].x = __float2bfloat16(x - __bfloat162float(H[k].x));
            L[k].y = __float2bfloat16(y - __bfloat162float(H[k].y));
        }
#pragma unroll
        for (int k=0;k<4;k++){
            *(__nv_bfloat162*)&PH[base + j0 + 2*k] = H[k];
            *(__nv_bfloat162*)&PL[base + j0 + 2*k] = L[k];
        }
        return;
    }

    // ---- scan (R13-proven; incremental evict stores + progress publish) ----
    const int z = blockIdx.x;
    const float* Pz = P + (long long)z * Sc * Sc;
    const int j0 = tid * 8;
    const float INFV = __int_as_float(0x7f800000);

    __shared__ uint4 part[2][4];
    __shared__ float swc[CBc];

    for (int i = tid; i < CBc; i += 128) swc[i] = g_wcoef[i];
    __syncthreads();

    float sel[8];
#pragma unroll
    for (int k=0;k<8;k++) sel[k] = 0.f;
#pragma unroll 4
    for (int i = 0; i < CBc; i++){
        float w = swc[i];
        float4 a = *(const float4*)&Pz[(long long)i*Sc + j0];
        float4 b = *(const float4*)&Pz[(long long)i*Sc + j0 + 4];
        sel[0] += w*a.x; sel[1] += w*a.y; sel[2] += w*a.z; sel[3] += w*a.w;
        sel[4] += w*b.x; sel[5] += w*b.y; sel[6] += w*b.z; sel[7] += w*b.w;
    }

    float scur[8], snxt[8], sfar[8];
    {
        float4 a, b;
        a = *(const float4*)&Pz[(long long)CBc*Sc + j0];
        b = *(const float4*)&Pz[(long long)CBc*Sc + j0 + 4];
        scur[0]=a.x;scur[1]=a.y;scur[2]=a.z;scur[3]=a.w;
        scur[4]=b.x;scur[5]=b.y;scur[6]=b.z;scur[7]=b.w;
        a = *(const float4*)&Pz[(long long)(CBc+1)*Sc + j0];
        b = *(const float4*)&Pz[(long long)(CBc+1)*Sc + j0 + 4];
        snxt[0]=a.x;snxt[1]=a.y;snxt[2]=a.z;snxt[3]=a.w;
        snxt[4]=b.x;snxt[5]=b.y;snxt[6]=b.z;snxt[7]=b.w;
        a = *(const float4*)&Pz[(long long)(CBc+2)*Sc + j0];
        b = *(const float4*)&Pz[(long long)(CBc+2)*Sc + j0 + 4];
        sfar[0]=a.x;sfar[1]=a.y;sfar[2]=a.z;sfar[3]=a.w;
        sfar[4]=b.x;sfar[5]=b.y;sfar[6]=b.z;sfar[7]=b.w;
    }

    float total;
    {
        float ps = 0.f;
#pragma unroll
        for (int k=0;k<8;k++) ps += scur[k];
#pragma unroll
        for (int o=16;o;o>>=1) ps += __shfl_xor_sync(0xffffffffu, ps, o);
        if (lane == 0) part[0][wid] = make_uint4(0u,0u,0u,__float_as_uint(ps));
        __syncthreads();
        total = 0.f;
#pragma unroll
        for (int w=0;w<4;w++) total += __uint_as_float(part[0][w].w);
    }

    for (int t = CBc; t <= Sc - 2; t++){
        const int par = t & 1;
        const float inv = 1.f / total;

#pragma unroll
        for (int k=0;k<8;k++){
            bool alive = (sel[k] < INFV);
            sel[k] = alive ? (FFc*sel[k] + scur[k]*inv) : INFV;
        }

        const int hi = t - RBc;
        unsigned long long key = ~0ull;
        float scn = 0.f;
#pragma unroll
        for (int k=0;k<8;k++){
            int j = j0 + k;
            if (j >= SBc && j <= hi){
                unsigned long long kk =
                    (((unsigned long long)__float_as_uint(sel[k])) << 32) | (unsigned)j;
                if (kk < key){ key = kk; scn = snxt[k]; }
            }
        }
        float ps = 0.f;
#pragma unroll
        for (int k=0;k<8;k++) if (sel[k] < INFV) ps += snxt[k];

        uint32_t sb32 = (uint32_t)(key>>32);
        uint32_t jpart = (uint32_t)key;
        uint32_t mn = __reduce_min_sync(0xffffffffu, sb32);
        uint32_t jc = (sb32==mn) ? jpart : 0xffffffffu;
        uint32_t jm = __reduce_min_sync(0xffffffffu, jc);
        uint32_t bal = __ballot_sync(0xffffffffu, (sb32==mn) && (jpart==jm));
        int src = __ffs(bal)-1;
        float wscn = __shfl_sync(0xffffffffu, scn, src);
#pragma unroll
        for (int o=16;o;o>>=1) ps += __shfl_xor_sync(0xffffffffu, ps, o);

        if (lane == 0)
            part[par][wid] = make_uint4(jm, mn,
                                        __float_as_uint(wscn), __float_as_uint(ps));
        __syncthreads();

        // publish progress every 16 steps: evictions through t-1 are ordered
        // by the barrier above; cumulative release fence makes them visible.
        if (tid == 0 && (t & 15) == 0){
            __threadfence();
            g_prog[z] = t - 1;
        }

        unsigned long long bk = ~0ull;
        float bscn = 0.f, raw = 0.f;
#pragma unroll
        for (int w=0;w<4;w++){
            uint4 q = part[par][w];
            unsigned long long k2 = (((unsigned long long)q.y)<<32) | q.x;
            if (k2 < bk){ bk = k2; bscn = __uint_as_float(q.z); }
            raw += __uint_as_float(q.w);
        }
        int mi = (int)(bk & 0xffffffffu);

        if (mi >= j0 && mi < j0 + 8){
            sel[mi - j0] = INFV;
            evict[z*Sc + mi] = t;               // incremental store
        }
        total = raw - bscn;

#pragma unroll
        for (int k=0;k<8;k++){ scur[k] = snxt[k]; snxt[k] = sfar[k]; }
        if (t + 3 <= Sc - 1){
            float4 a = *(const float4*)&Pz[(long long)(t+3)*Sc + j0];
            float4 b = *(const float4*)&Pz[(long long)(t+3)*Sc + j0 + 4];
            sfar[0]=a.x;sfar[1]=a.y;sfar[2]=a.z;sfar[3]=a.w;
            sfar[4]=b.x;sfar[5]=b.y;sfar[6]=b.z;sfar[7]=b.w;
        }
    }

    // final publish: all evictions done
    __syncthreads();
    if (tid == 0){
        __threadfence();
        g_prog[z] = Sc;
    }
}

// ----------------------------------------------------------------------------
// Launch
// ----------------------------------------------------------------------------
extern "C" void kernel_launch(void* const* d_in, const int* in_sizes, int n_in,
                              void* d_out, int out_size)
{
    (void)in_sizes; (void)n_in; (void)out_size;
    const float* hs = (const float*)d_in[0];
    const float* wq = (const float*)d_in[1];
    const float* wk = (const float*)d_in[2];
    const float* wv = (const float*)d_in[3];
    const float* wo = (const float*)d_in[4];
    float* out = (float*)d_out;

    float *lin, *P;
    __nv_bfloat16 *hsH, *hsL, *wH, *wL;
    __nv_bfloat16 *QH, *QL, *KH, *KL, *VH, *VL, *PH, *PL, *cH, *cL;
    int* ev;
    cudaGetSymbolAddress((void**)&lin, g_lin);
    cudaGetSymbolAddress((void**)&hsH, g_hsH);  cudaGetSymbolAddress((void**)&hsL, g_hsL);
    cudaGetSymbolAddress((void**)&wH, g_wH);    cudaGetSymbolAddress((void**)&wL, g_wL);
    cudaGetSymbolAddress((void**)&QH, g_QH);    cudaGetSymbolAddress((void**)&QL, g_QL);
    cudaGetSymbolAddress((void**)&KH, g_KH);    cudaGetSymbolAddress((void**)&KL, g_KL);
    cudaGetSymbolAddress((void**)&VH, g_VH);    cudaGetSymbolAddress((void**)&VL, g_VL);
    cudaGetSymbolAddress((void**)&P, g_P);
    cudaGetSymbolAddress((void**)&PH, g_PH);    cudaGetSymbolAddress((void**)&PL, g_PL);
    cudaGetSymbolAddress((void**)&cH, g_cH);    cudaGetSymbolAddress((void**)&cL, g_cL);
    cudaGetSymbolAddress((void**)&ev, g_evict);

    cudaFuncSetAttribute((const void*)gemm_mma<256,256,true,false,false,false>,
                         cudaFuncAttributeMaxDynamicSharedMemorySize, GSMEM_TOTAL);
    cudaFuncSetAttribute((const void*)gemm_mma<256,256,false,true,false,false>,
                         cudaFuncAttributeMaxDynamicSharedMemorySize, GSMEM_TOTAL);
    cudaFuncSetAttribute((const void*)gemm_mma<256,128,true,false,true,true>,
                         cudaFuncAttributeMaxDynamicSharedMemorySize, GSMEM_TOTAL);

    const float qk_scale = 0.08838834764831845f;  // 1/sqrt(128)
    const int splitBlocks = NELT/8/256;

    // 0) tables + evict/progress init
    rope_tables<<<(Sc*64)/256, 256>>>();

    // 1) bf16 hi/lo splits
    split_plain<<<splitBlocks, 256>>>(hs, hsH, hsL, NELT);
    split_w4<<<dim3(splitBlocks,4), 256>>>(wq, wk, wv, wo, wH, wL);

    // 2) Fused QKV projections
    gemm_mma<256,256,true,false,false,false><<<dim3(8,16,3), 256, GSMEM_TOTAL>>>(
        hsH, hsL, wH, wL, lin, nullptr, nullptr, HIDc, HIDc, HIDc,
        0, (long long)HIDc*HIDc, (long long)NELT, 0, 1, 1.f);

    // 3) RoPE + layout + split
    rope_split<<<NELT/256, 256>>>();

    // 4) QK^T causal, scaled
    gemm_mma<256,256,false,true,false,false><<<dim3(4,8,ZB), 256, GSMEM_TOTAL>>>(
        QH, QL, KH, KL, P, nullptr, nullptr, HDc, HDc, Sc,
        (long long)Sc*HDc, (long long)Sc*HDc,
        (long long)Sc*Sc, 0, 1, qk_scale);

    // 5) softmax
    softmax_causal<<<ZB*Sc, 256>>>(P);

    // 6) FAT: scan + head maskrenorm + progress-gated tail maskrenorm
    scan_fat<<<ZB + ZB*HEADROWS + ZB*TAILROWS, 128>>>(P, ev, PH, PL);

    // 7) PV -> ctx
    gemm_mma<256,128,true,false,true,true><<<dim3(1,8,ZB), 256, GSMEM_TOTAL>>>(
        PH, PL, VH, VL, nullptr, cH, cL, Sc, HDc, HIDc,
        (long long)Sc*Sc, (long long)Sc*HDc,
        (long long)Sc*HIDc, (long long)HDc, NHc, 1.f);

    // 8) output projection
    gemm_mma<256,256,true,false,false,false><<<dim3(8,16,1), 256, GSMEM_TOTAL>>>(
        cH, cL, wH + 3*(size_t)HIDc*HIDc, wL + 3*(size_t)HIDc*HIDc, out,
        nullptr, nullptr, HIDc, HIDc, HIDc, 0, 0, 0, 0, 1, 1.f);
}

// round 15
// speedup vs baseline: 1.0080x; 1.0080x over previous
#include <cuda_runtime.h>
#include <cuda_bf16.h>
#include <math.h>
#include <float.h>
#include <stdint.h>

// Problem constants
#define Bc    2
#define Sc    1024
#define HIDc  2048
#define NHc   16
#define HDc   128
#define SBc   20
#define RBc   82
#define CBc   163
#define FFc   0.9f
#define BSc   (Bc*Sc)          // 2048
#define ZB    (Bc*NHc)         // 32
#define NELT  (BSc*HIDc)       // 4M
#define HEADROWS (CBc+1)       // 164 rows with no evict dependency
#define TAILROWS (Sc-HEADROWS) // 860

// ----------------------------------------------------------------------------
// Scratch
// ----------------------------------------------------------------------------
__device__ __align__(1024) float g_lin[3*NELT];
__device__ __align__(1024) __nv_bfloat16 g_hsH[NELT];
__device__ __align__(1024) __nv_bfloat16 g_hsL[NELT];
__device__ __align__(1024) __nv_bfloat16 g_wH[4*HIDc*HIDc];
__device__ __align__(1024) __nv_bfloat16 g_wL[4*HIDc*HIDc];
__device__ __align__(1024) __nv_bfloat16 g_QH[ZB*Sc*HDc];
__device__ __align__(1024) __nv_bfloat16 g_QL[ZB*Sc*HDc];
__device__ __align__(1024) __nv_bfloat16 g_KH[ZB*Sc*HDc];
__device__ __align__(1024) __nv_bfloat16 g_KL[ZB*Sc*HDc];
__device__ __align__(1024) __nv_bfloat16 g_VH[ZB*Sc*HDc];
__device__ __align__(1024) __nv_bfloat16 g_VL[ZB*Sc*HDc];
__device__ __align__(1024) float g_P[(size_t)ZB*Sc*Sc];
__device__ __align__(1024) __nv_bfloat16 g_PH[(size_t)ZB*Sc*Sc];
__device__ __align__(1024) __nv_bfloat16 g_PL[(size_t)ZB*Sc*Sc];
__device__ __align__(1024) __nv_bfloat16 g_cH[NELT];
__device__ __align__(1024) __nv_bfloat16 g_cL[NELT];
__device__ int g_evict[ZB*Sc];
__device__ __align__(128) int g_prog[ZB*32];   // one counter per 128B line
__device__ float g_tcos[Sc*64];
__device__ float g_tsin[Sc*64];
__device__ float g_wcoef[CBc];

// ----------------------------------------------------------------------------
// PTX helpers
// ----------------------------------------------------------------------------
__device__ __forceinline__ uint32_t smem_u32(const void* p){
    uint32_t a;
    asm("{ .reg .u64 t; cvta.to.shared.u64 t, %1; cvt.u32.u64 %0, t; }":"=r"(a):"l"(p));
    return a;
}
__device__ __forceinline__ void cp16(uint32_t d, const void* s){
    asm volatile("cp.async.cg.shared.global [%0], [%1], 16;"::"r"(d),"l"(s));
}
#define CP_COMMIT() asm volatile("cp.async.commit_group;":::"memory")
#define CP_WAIT(n)  asm volatile("cp.async.wait_group %0;"::"n"(n):"memory")

__device__ __forceinline__ void ldsm4(uint32_t r[4], uint32_t a){
    asm volatile("ldmatrix.sync.aligned.m8n8.x4.shared.b16 {%0,%1,%2,%3}, [%4];"
        : "=r"(r[0]),"=r"(r[1]),"=r"(r[2]),"=r"(r[3]) : "r"(a));
}
__device__ __forceinline__ void ldsm4t(uint32_t r[4], uint32_t a){
    asm volatile("ldmatrix.sync.aligned.m8n8.x4.trans.shared.b16 {%0,%1,%2,%3}, [%4];"
        : "=r"(r[0]),"=r"(r[1]),"=r"(r[2]),"=r"(r[3]) : "r"(a));
}
__device__ __forceinline__ void mma16816(float d[4], const uint32_t a[4], const uint32_t b[2]){
    asm volatile("mma.sync.aligned.m16n8k16.row.col.f32.bf16.bf16.f32 "
        "{%0,%1,%2,%3},{%4,%5,%6,%7},{%8,%9},{%0,%1,%2,%3};"
        : "+f"(d[0]),"+f"(d[1]),"+f"(d[2]),"+f"(d[3])
        : "r"(a[0]),"r"(a[1]),"r"(a[2]),"r"(a[3]),"r"(b[0]),"r"(b[1]));
}

#define GSMEM_TOTAL 196608   // 192 KB

template<int NROWS, int NTH>
__device__ __forceinline__ void copy_rk(uint32_t dst, const __nv_bfloat16* src,
                                        int ld, int tid){
#pragma unroll
    for (int i=0;i<NROWS*8/NTH;i++){
        int idx = tid + i*NTH;
        int r = idx>>3, c = idx&7;
        uint32_t sw = (uint32_t)(r*128) + (uint32_t)(((c ^ (r&7))<<4));
        cp16(dst + sw, (const char*)src + ((long long)r*ld + c*8)*2);
    }
}
template<int NCOLS, int NTH>
__device__ __forceinline__ void copy_kn(uint32_t dst, const __nv_bfloat16* src,
                                        int ld, int tid){
    const int CPR = NCOLS/8;
#pragma unroll
    for (int i=0;i<64*CPR/NTH;i++){
        int idx = tid + i*NTH;
        int r = idx/CPR, c = idx%CPR;
        uint32_t sw = (uint32_t)(r*(NCOLS*2)) + (uint32_t)(((c ^ (r&7))<<4));
        cp16(dst + sw, (const char*)src + ((long long)r*ld + c*8)*2);
    }
}

// ----------------------------------------------------------------------------
// HMMA GEMM (R9-proven)
// ----------------------------------------------------------------------------
template<int NTH, int NT, bool BKN, bool CAUSAL, bool SPLITOUT, bool KTRUNC>
__global__ void __launch_bounds__(NTH) gemm_mma(
    const __nv_bfloat16* __restrict__ Ah, const __nv_bfloat16* __restrict__ Al,
    const __nv_bfloat16* __restrict__ Bh, const __nv_bfloat16* __restrict__ Bl,
    float* __restrict__ C,
    __nv_bfloat16* __restrict__ CH, __nv_bfloat16* __restrict__ CL,
    int K, int ldb, int ldc,
    long long sA, long long sB, long long sCo, long long sCi, int ndiv, float alpha)
{
    const int my = KTRUNC ? (gridDim.y - 1 - blockIdx.y) : blockIdx.y;
    const int m0 = my*128, n0 = blockIdx.x*NT, z = blockIdx.z;
    if (CAUSAL && n0 > m0 + 127) return;
    const int NN8 = NT/32;
    const int NHALF = NN8/4;
    const int MWT = (NTH==512) ? 32 : 64;
    const int MB  = MWT/16;
    const int TILEA = 16384;
    const int TILEBB = NT*128;
    const int STG = 2*TILEA + 2*TILEBB;
    const int NS = (NT==256) ? 2 : 3;

    extern __shared__ __align__(1024) char smem[];
    const uint32_t sb = smem_u32(smem);
    Ah += (long long)z*sA; Al += (long long)z*sA;
    Bh += (long long)z*sB; Bl += (long long)z*sB;
    long long coff = (long long)(z/ndiv)*sCo + (long long)(z%ndiv)*sCi;
    if (SPLITOUT){ CH += coff; CL += coff; } else { C += coff; }

    const int tid = threadIdx.x, lane = tid&31, wid = tid>>5;
    const int wm = wid>>2, wn = wid&3;

    float acc[MB][NN8][4];
#pragma unroll
    for (int a=0;a<MB;a++)
#pragma unroll
        for (int b=0;b<NN8;b++)
#pragma unroll
            for (int c=0;c<4;c++) acc[a][b][c] = 0.f;

    const int nch = KTRUNC ? ((m0+128)>>6) : (K>>6);

#define LOAD_CHUNK(cc, ss) do{ \
    uint32_t bbase = sb + (uint32_t)(ss)*STG; \
    copy_rk<128,NTH>(bbase,         Ah + (long long)m0*K + (cc)*64, K, tid); \
    copy_rk<128,NTH>(bbase + TILEA, Al + (long long)m0*K + (cc)*64, K, tid); \
    if (BKN){ \
        copy_kn<NT,NTH>(bbase + 2*TILEA,          Bh + (long long)(cc)*64*ldb + n0, ldb, tid); \
        copy_kn<NT,NTH>(bbase + 2*TILEA + TILEBB, Bl + (long long)(cc)*64*ldb + n0, ldb, tid); \
    } else { \
        copy_rk<NT,NTH>(bbase + 2*TILEA,          Bh + (long long)n0*K + (cc)*64, K, tid); \
        copy_rk<NT,NTH>(bbase + 2*TILEA + TILEBB, Bl + (long long)n0*K + (cc)*64, K, tid); \
    } \
    CP_COMMIT(); }while(0)

    LOAD_CHUNK(0, 0);
    if (NS > 1 && nch > 1) LOAD_CHUNK(1, 1);
    if (NS > 2 && nch > 2) LOAD_CHUNK(2, 2);

    const uint32_t axor = (uint32_t)(lane&7);

    for (int c=0; c<nch; c++){
        int pend = nch-1-c; if (pend > NS-1) pend = NS-1;
        if (pend >= 2) CP_WAIT(2);
        else if (pend == 1) CP_WAIT(1);
        else CP_WAIT(0);
        __syncthreads();
        uint32_t base = sb + (uint32_t)(c % NS)*STG;
#pragma unroll
        for (int ks=0; ks<4; ks++){
#pragma unroll
            for (int half=0; half<NHALF; half++){
                uint32_t bh[4][2], bl[4][2];
#pragma unroll
                for (int nb=0;nb<2;nb++){
                    uint32_t t[4];
                    int gg = half*2 + nb;
                    if (BKN){
                        uint32_t row = (uint32_t)(ks*16 + (lane&7) + (((lane>>3)&1)<<3));
                        uint32_t ch  = ((uint32_t)(wn*NN8 + gg*2 + (lane>>4)) ^ axor);
                        uint32_t ad  = base + 2*TILEA + row*(NT*2) + (ch<<4);
                        ldsm4t(t, ad);
                        bh[2*nb][0]=t[0]; bh[2*nb][1]=t[1]; bh[2*nb+1][0]=t[2]; bh[2*nb+1][1]=t[3];
                        ldsm4t(t, ad + TILEBB);
                        bl[2*nb][0]=t[0]; bl[2*nb][1]=t[1]; bl[2*nb+1][0]=t[2]; bl[2*nb+1][1]=t[3];
                    } else {
                        uint32_t row = (uint32_t)(wn*(NT/4) + gg*16 + (lane&7) + ((lane>>4)<<3));
                        uint32_t ch  = ((uint32_t)(ks*2 + ((lane>>3)&1)) ^ axor);
                        uint32_t ad  = base + 2*TILEA + row*128 + (ch<<4);
                        ldsm4(t, ad);
                        bh[2*nb][0]=t[0]; bh[2*nb][1]=t[1]; bh[2*nb+1][0]=t[2]; bh[2*nb+1][1]=t[3];
                        ldsm4(t, ad + TILEBB);
                        bl[2*nb][0]=t[0]; bl[2*nb][1]=t[1]; bl[2*nb+1][0]=t[2]; bl[2*nb+1][1]=t[3];
                    }
                }
#pragma unroll
                for (int mb=0;mb<MB;mb++){
                    uint32_t ah[4], al[4];
                    uint32_t row = (uint32_t)(wm*MWT + mb*16 + (lane&15));
                    uint32_t col = (((uint32_t)(ks*2 + (lane>>4)) ^ (row&7u))<<4);
                    uint32_t ad = base + row*128 + col;
                    ldsm4(ah, ad);
                    ldsm4(al, ad + TILEA);
#pragma unroll
                    for (int n8=0;n8<4;n8++){
                        int g8 = half*4 + n8;
                        mma16816(acc[mb][g8], ah, bh[n8]);
                        mma16816(acc[mb][g8], ah, bl[n8]);
                        mma16816(acc[mb][g8], al, bh[n8]);
                    }
                }
            }
        }
        __syncthreads();
        if (c + NS < nch) LOAD_CHUNK(c + NS, c % NS);
    }
#undef LOAD_CHUNK

#pragma unroll
    for (int mb=0;mb<MB;mb++){
        int r0 = m0 + wm*MWT + mb*16 + (lane>>2);
#pragma unroll
        for (int n8=0;n8<NN8;n8++){
            int cc = n0 + wn*(NT/4) + n8*8 + (lane&3)*2;
            float vx0 = acc[mb][n8][0]*alpha, vy0 = acc[mb][n8][1]*alpha;
            float vx1 = acc[mb][n8][2]*alpha, vy1 = acc[mb][n8][3]*alpha;
            if (SPLITOUT){
                __nv_bfloat162 h0, l0, h1, l1;
                h0.x = __float2bfloat16(vx0); h0.y = __float2bfloat16(vy0);
                l0.x = __float2bfloat16(vx0 - __bfloat162float(h0.x));
                l0.y = __float2bfloat16(vy0 - __bfloat162float(h0.y));
                h1.x = __float2bfloat16(vx1); h1.y = __float2bfloat16(vy1);
                l1.x = __float2bfloat16(vx1 - __bfloat162float(h1.x));
                l1.y = __float2bfloat16(vy1 - __bfloat162float(h1.y));
                *(__nv_bfloat162*)&CH[(long long)r0*ldc + cc] = h0;
                *(__nv_bfloat162*)&CL[(long long)r0*ldc + cc] = l0;
                *(__nv_bfloat162*)&CH[(long long)(r0+8)*ldc + cc] = h1;
                *(__nv_bfloat162*)&CL[(long long)(r0+8)*ldc + cc] = l1;
            } else {
                float2 v0; v0.x = vx0; v0.y = vy0;
                float2 v1; v1.x = vx1; v1.y = vy1;
                *(float2*)&C[(long long)r0*ldc + cc] = v0;
                *(float2*)&C[(long long)(r0+8)*ldc + cc] = v1;
            }
        }
    }
}

// ----------------------------------------------------------------------------
// fp32 -> bf16 hi/lo split; 8 elems/thread
// ----------------------------------------------------------------------------
__device__ __forceinline__ void split_body(const float* __restrict__ X,
                                           __nv_bfloat16* __restrict__ H,
                                           __nv_bfloat16* __restrict__ L, int i)
{
    float4 v = *(const float4*)&X[i];
    float4 w = *(const float4*)&X[i+4];
    __nv_bfloat16 h0=__float2bfloat16(v.x), h1=__float2bfloat16(v.y);
    __nv_bfloat16 h2=__float2bfloat16(v.z), h3=__float2bfloat16(v.w);
    __nv_bfloat16 h4=__float2bfloat16(w.x), h5=__float2bfloat16(w.y);
    __nv_bfloat16 h6=__float2bfloat16(w.z), h7=__float2bfloat16(w.w);
    __nv_bfloat162 H01{h0,h1}, H23{h2,h3}, H45{h4,h5}, H67{h6,h7};
    *(__nv_bfloat162*)&H[i]   = H01; *(__nv_bfloat162*)&H[i+2] = H23;
    *(__nv_bfloat162*)&H[i+4] = H45; *(__nv_bfloat162*)&H[i+6] = H67;
    __nv_bfloat162 L01, L23, L45, L67;
    L01.x = __float2bfloat16(v.x - __bfloat162float(h0));
    L01.y = __float2bfloat16(v.y - __bfloat162float(h1));
    L23.x = __float2bfloat16(v.z - __bfloat162float(h2));
    L23.y = __float2bfloat16(v.w - __bfloat162float(h3));
    L45.x = __float2bfloat16(w.x - __bfloat162float(h4));
    L45.y = __float2bfloat16(w.y - __bfloat162float(h5));
    L67.x = __float2bfloat16(w.z - __bfloat162float(h6));
    L67.y = __float2bfloat16(w.w - __bfloat162float(h7));
    *(__nv_bfloat162*)&L[i]   = L01; *(__nv_bfloat162*)&L[i+2] = L23;
    *(__nv_bfloat162*)&L[i+4] = L45; *(__nv_bfloat162*)&L[i+6] = L67;
}

__global__ void split_plain(const float* __restrict__ X,
                            __nv_bfloat16* __restrict__ H,
                            __nv_bfloat16* __restrict__ L, int n)
{
    int i = (blockIdx.x*blockDim.x + threadIdx.x)*8;
    if (i < n) split_body(X, H, L, i);
}

__global__ void split_w4(const float* __restrict__ w0, const float* __restrict__ w1,
                         const float* __restrict__ w2, const float* __restrict__ w3,
                         __nv_bfloat16* __restrict__ H, __nv_bfloat16* __restrict__ L)
{
    const float* src = (blockIdx.y==0)?w0:(blockIdx.y==1)?w1:(blockIdx.y==2)?w2:w3;
    size_t off = (size_t)blockIdx.y * HIDc * HIDc;
    int i = (blockIdx.x*blockDim.x + threadIdx.x)*8;
    split_body(src, H + off, L + off, i);
}

// ----------------------------------------------------------------------------
// Tables + evict/progress init
// ----------------------------------------------------------------------------
__global__ void rope_tables()
{
    int idx = blockIdx.x*blockDim.x + threadIdx.x;
    int s = idx >> 6, i = idx & 63;
    double inv = pow(10000.0, -(double)i/64.0);
    double a = (double)s * inv;
    g_tcos[idx] = (float)cos(a);
    g_tsin[idx] = (float)sin(a);
    if (idx < CBc) g_wcoef[idx] = (float)pow((double)FFc, (double)(CBc-1-idx));
    if (idx < ZB*Sc) g_evict[idx] = 0x7fffffff;
    if (idx < ZB*32) g_prog[idx] = 0;
}

// ----------------------------------------------------------------------------
// RoPE + layout + split
// ----------------------------------------------------------------------------
__global__ void rope_split()
{
    long long idx = (long long)blockIdx.x * blockDim.x + threadIdx.x;
    if (idx >= (long long)NELT) return;

    int d = (int)(idx % HDc);
    int h = (int)((idx / HDc) % NHc);
    int s = (int)((idx / HIDc) % Sc);
    int b = (int)(idx / ((long long)Sc * HIDc));
    int z = b*NHc + h;

    long long lin = (long long)(b * Sc + s) * HIDc + h * HDc + d;
    long long out = (long long)(z * Sc + s) * HDc + d;

    const float* Qlin = g_lin;
    const float* Klin = g_lin + NELT;
    const float* Vlin = g_lin + 2*(long long)NELT;

    float q = Qlin[lin];
    float k = Klin[lin];
    float qr, kr;
    if (d < 64) { qr = -Qlin[lin + 64]; kr = -Klin[lin + 64]; }
    else        { qr =  Qlin[lin - 64]; kr =  Klin[lin - 64]; }

    int ti = (s<<6) + (d & 63);
    float c = g_tcos[ti], sn = g_tsin[ti];

    float qv = q * c + qr * sn;
    float kv = k * c + kr * sn;

    __nv_bfloat16 qh = __float2bfloat16(qv);
    g_QH[out] = qh; g_QL[out] = __float2bfloat16(qv - __bfloat162float(qh));
    __nv_bfloat16 kh = __float2bfloat16(kv);
    g_KH[out] = kh; g_KL[out] = __float2bfloat16(kv - __bfloat162float(kh));

    float vv = Vlin[lin];
    __nv_bfloat16 vh = __float2bfloat16(vv);
    g_VH[out] = vh; g_VL[out] = __float2bfloat16(vv - __bfloat162float(vh));
}

// ----------------------------------------------------------------------------
// Causal row softmax (R9)
// ----------------------------------------------------------------------------
__global__ void __launch_bounds__(256) softmax_causal(float* __restrict__ P)
{
    __shared__ float smA[9];
    __shared__ float smB[9];
    long long row = blockIdx.x;
    int r = (int)(row & (Sc-1));
    float* p = P + row * Sc;
    const int tid = threadIdx.x;
    const int lane = tid & 31, wid = tid >> 5;

    float v[4];
    float mx = -FLT_MAX;
#pragma unroll
    for (int i = 0; i < 4; i++) {
        int jj = tid + i*256;
        v[i] = (jj <= r) ? p[jj] : -FLT_MAX;
        mx = fmaxf(mx, v[i]);
    }
#pragma unroll
    for (int o = 16; o; o >>= 1) mx = fmaxf(mx, __shfl_xor_sync(0xffffffffu, mx, o));
    if (lane == 0) smA[wid] = mx;
    __syncthreads();
    if (tid < 8) {
        float x = smA[tid];
#pragma unroll
        for (int o = 4; o; o >>= 1) x = fmaxf(x, __shfl_xor_sync(0xffu, x, o));
        if (tid == 0) smA[8] = x;
    }
    __syncthreads();
    mx = smA[8];

    float sum = 0.f;
#pragma unroll
    for (int i = 0; i < 4; i++) { v[i] = expf(v[i] - mx); sum += v[i]; }
#pragma unroll
    for (int o = 16; o; o >>= 1) sum += __shfl_xor_sync(0xffffffffu, sum, o);
    if (lane == 0) smB[wid] = sum;
    __syncthreads();
    if (tid < 8) {
        float x = smB[tid];
#pragma unroll
        for (int o = 4; o; o >>= 1) x += __shfl_xor_sync(0xffu, x, o);
        if (tid == 0) smB[8] = x;
    }
    __syncthreads();
    sum = smB[8];

    float inv = 1.f / sum;
#pragma unroll
    for (int i = 0; i < 4; i++) p[tid + i * 256] = v[i] * inv;
}

// ----------------------------------------------------------------------------
// FAT kernel:
//  blocks [0,ZB)                : eviction scan (publishes padded progress)
//  blocks [ZB, ZB+ZB*HEADROWS)  : head maskrenorm (no dependency)
//  blocks >= ZB+ZB*HEADROWS     : tail maskrenorm, low-rate poll on padded
//                                 per-z counters (L2-only loads + nanosleep).
// Tail row r needs only evictions with t < r (INT_MAX -> t transition is
// predicate-neutral for t >= r).
// ----------------------------------------------------------------------------
__global__ void __launch_bounds__(128) scan_fat(const float* __restrict__ P,
                                               int* __restrict__ evict,
                                               __nv_bfloat16* __restrict__ PH,
                                               __nv_bfloat16* __restrict__ PL)
{
    const int tid = threadIdx.x;
    const int lane = tid & 31, wid = tid >> 5;

    if (blockIdx.x >= ZB){
        __shared__ float hs[4];
        int bi = blockIdx.x - ZB;
        int z, r;
        bool tail = (bi >= ZB*HEADROWS);
        if (!tail){ z = bi / HEADROWS; r = bi % HEADROWS; }
        else {
            int ti2 = bi - ZB*HEADROWS;         // r-ascending ordering
            r = HEADROWS + (ti2 >> 5);
            z = ti2 & 31;
        }
        long long row = (long long)z * Sc + r;
        const float* p = P + row * Sc;
        const int* e = evict + z * Sc;
        int j0 = tid * 8;

        if (tail){
            if (tid == 0){
                const int* pp = g_prog + z*32;
                int target = r - 1;
                for (;;){
                    int pr;
                    asm volatile("ld.global.cg.b32 %0, [%1];" : "=r"(pr) : "l"(pp));
                    if (pr >= target) break;
                    __nanosleep(1024);
                }
                __threadfence();                 // acquire before barrier
            }
            __syncthreads();
        }

        float v[8];
        float4 a = *(const float4*)&p[j0];
        float4 b = *(const float4*)&p[j0+4];
        v[0]=a.x;v[1]=a.y;v[2]=a.z;v[3]=a.w;v[4]=b.x;v[5]=b.y;v[6]=b.z;v[7]=b.w;
        if (tail){
#pragma unroll
            for (int k=0;k<8;k++)
                if (e[j0+k] < r) v[k] = 0.f;
        }
        float sum = 0.f;
#pragma unroll
        for (int k=0;k<8;k++) sum += v[k];
#pragma unroll
        for (int o=16;o;o>>=1) sum += __shfl_xor_sync(0xffffffffu, sum, o);
        if (lane == 0) hs[wid] = sum;
        __syncthreads();
        float total = hs[0]+hs[1]+hs[2]+hs[3];
        float inv = 1.f / total;
        long long base = row * Sc;
        __nv_bfloat162 H[4], L[4];
#pragma unroll
        for (int k=0;k<4;k++){
            float x = v[2*k]*inv, y = v[2*k+1]*inv;
            H[k].x = __float2bfloat16(x); H[k].y = __float2bfloat16(y);
            L[k].x = __float2bfloat16(x - __bfloat162float(H[k].x));
            L[k].y = __float2bfloat16(y - __bfloat162float(H[k].y));
        }
#pragma unroll
        for (int k=0;k<4;k++){
            *(__nv_bfloat162*)&PH[base + j0 + 2*k] = H[k];
            *(__nv_bfloat162*)&PL[base + j0 + 2*k] = L[k];
        }
        return;
    }

    // ---- scan (R13-proven; incremental evict stores + padded progress) ----
    const int z = blockIdx.x;
    const float* Pz = P + (long long)z * Sc * Sc;
    const int j0 = tid * 8;
    const float INFV = __int_as_float(0x7f800000);

    __shared__ uint4 part[2][4];
    __shared__ float swc[CBc];

    for (int i = tid; i < CBc; i += 128) swc[i] = g_wcoef[i];
    __syncthreads();

    float sel[8];
#pragma unroll
    for (int k=0;k<8;k++) sel[k] = 0.f;
#pragma unroll 4
    for (int i = 0; i < CBc; i++){
        float w = swc[i];
        float4 a = *(const float4*)&Pz[(long long)i*Sc + j0];
        float4 b = *(const float4*)&Pz[(long long)i*Sc + j0 + 4];
        sel[0] += w*a.x; sel[1] += w*a.y; sel[2] += w*a.z; sel[3] += w*a.w;
        sel[4] += w*b.x; sel[5] += w*b.y; sel[6] += w*b.z; sel[7] += w*b.w;
    }

    float scur[8], snxt[8], sfar[8];
    {
        float4 a, b;
        a = *(const float4*)&Pz[(long long)CBc*Sc + j0];
        b = *(const float4*)&Pz[(long long)CBc*Sc + j0 + 4];
        scur[0]=a.x;scur[1]=a.y;scur[2]=a.z;scur[3]=a.w;
        scur[4]=b.x;scur[5]=b.y;scur[6]=b.z;scur[7]=b.w;
        a = *(const float4*)&Pz[(long long)(CBc+1)*Sc + j0];
        b = *(const float4*)&Pz[(long long)(CBc+1)*Sc + j0 + 4];
        snxt[0]=a.x;snxt[1]=a.y;snxt[2]=a.z;snxt[3]=a.w;
        snxt[4]=b.x;snxt[5]=b.y;snxt[6]=b.z;snxt[7]=b.w;
        a = *(const float4*)&Pz[(long long)(CBc+2)*Sc + j0];
        b = *(const float4*)&Pz[(long long)(CBc+2)*Sc + j0 + 4];
        sfar[0]=a.x;sfar[1]=a.y;sfar[2]=a.z;sfar[3]=a.w;
        sfar[4]=b.x;sfar[5]=b.y;sfar[6]=b.z;sfar[7]=b.w;
    }

    float total;
    {
        float ps = 0.f;
#pragma unroll
        for (int k=0;k<8;k++) ps += scur[k];
#pragma unroll
        for (int o=16;o;o>>=1) ps += __shfl_xor_sync(0xffffffffu, ps, o);
        if (lane == 0) part[0][wid] = make_uint4(0u,0u,0u,__float_as_uint(ps));
        __syncthreads();
        total = 0.f;
#pragma unroll
        for (int w=0;w<4;w++) total += __uint_as_float(part[0][w].w);
    }

    for (int t = CBc; t <= Sc - 2; t++){
        const int par = t & 1;
        const float inv = 1.f / total;

#pragma unroll
        for (int k=0;k<8;k++){
            bool alive = (sel[k] < INFV);
            sel[k] = alive ? (FFc*sel[k] + scur[k]*inv) : INFV;
        }

        const int hi = t - RBc;
        unsigned long long key = ~0ull;
        float scn = 0.f;
#pragma unroll
        for (int k=0;k<8;k++){
            int j = j0 + k;
            if (j >= SBc && j <= hi){
                unsigned long long kk =
                    (((unsigned long long)__float_as_uint(sel[k])) << 32) | (unsigned)j;
                if (kk < key){ key = kk; scn = snxt[k]; }
            }
        }
        float ps = 0.f;
#pragma unroll
        for (int k=0;k<8;k++) if (sel[k] < INFV) ps += snxt[k];

        uint32_t sb32 = (uint32_t)(key>>32);
        uint32_t jpart = (uint32_t)key;
        uint32_t mn = __reduce_min_sync(0xffffffffu, sb32);
        uint32_t jc = (sb32==mn) ? jpart : 0xffffffffu;
        uint32_t jm = __reduce_min_sync(0xffffffffu, jc);
        uint32_t bal = __ballot_sync(0xffffffffu, (sb32==mn) && (jpart==jm));
        int src = __ffs(bal)-1;
        float wscn = __shfl_sync(0xffffffffu, scn, src);
#pragma unroll
        for (int o=16;o;o>>=1) ps += __shfl_xor_sync(0xffffffffu, ps, o);

        if (lane == 0)
            part[par][wid] = make_uint4(jm, mn,
                                        __float_as_uint(wscn), __float_as_uint(ps));
        __syncthreads();

        // publish progress every 16 steps (evictions through t-1 are barrier-
        // ordered; release fence makes them device-visible).
        if (tid == 0 && (t & 15) == 0){
            __threadfence();
            g_prog[z*32] = t - 1;
        }

        unsigned long long bk = ~0ull;
        float bscn = 0.f, raw = 0.f;
#pragma unroll
        for (int w=0;w<4;w++){
            uint4 q = part[par][w];
            unsigned long long k2 = (((unsigned long long)q.y)<<32) | q.x;
            if (k2 < bk){ bk = k2; bscn = __uint_as_float(q.z); }
            raw += __uint_as_float(q.w);
        }
        int mi = (int)(bk & 0xffffffffu);

        if (mi >= j0 && mi < j0 + 8){
            sel[mi - j0] = INFV;
            evict[z*Sc + mi] = t;               // incremental store
        }
        total = raw - bscn;

#pragma unroll
        for (int k=0;k<8;k++){ scur[k] = snxt[k]; snxt[k] = sfar[k]; }
        if (t + 3 <= Sc - 1){
            float4 a = *(const float4*)&Pz[(long long)(t+3)*Sc + j0];
            float4 b = *(const float4*)&Pz[(long long)(t+3)*Sc + j0 + 4];
            sfar[0]=a.x;sfar[1]=a.y;sfar[2]=a.z;sfar[3]=a.w;
            sfar[4]=b.x;sfar[5]=b.y;sfar[6]=b.z;sfar[7]=b.w;
        }
    }

    __syncthreads();
    if (tid == 0){
        __threadfence();
        g_prog[z*32] = Sc;
    }
}

// ----------------------------------------------------------------------------
// Launch
// ----------------------------------------------------------------------------
extern "C" void kernel_launch(void* const* d_in, const int* in_sizes, int n_in,
                              void* d_out, int out_size)
{
    (void)in_sizes; (void)n_in; (void)out_size;
    const float* hs = (const float*)d_in[0];
    const float* wq = (const float*)d_in[1];
    const float* wk = (const float*)d_in[2];
    const float* wv = (const float*)d_in[3];
    const float* wo = (const float*)d_in[4];
    float* out = (float*)d_out;

    float *lin, *P;
    __nv_bfloat16 *hsH, *hsL, *wH, *wL;
    __nv_bfloat16 *QH, *QL, *KH, *KL, *VH, *VL, *PH, *PL, *cH, *cL;
    int* ev;
    cudaGetSymbolAddress((void**)&lin, g_lin);
    cudaGetSymbolAddress((void**)&hsH, g_hsH);  cudaGetSymbolAddress((void**)&hsL, g_hsL);
    cudaGetSymbolAddress((void**)&wH, g_wH);    cudaGetSymbolAddress((void**)&wL, g_wL);
    cudaGetSymbolAddress((void**)&QH, g_QH);    cudaGetSymbolAddress((void**)&QL, g_QL);
    cudaGetSymbolAddress((void**)&KH, g_KH);    cudaGetSymbolAddress((void**)&KL, g_KL);
    cudaGetSymbolAddress((void**)&VH, g_VH);    cudaGetSymbolAddress((void**)&VL, g_VL);
    cudaGetSymbolAddress((void**)&P, g_P);
    cudaGetSymbolAddress((void**)&PH, g_PH);    cudaGetSymbolAddress((void**)&PL, g_PL);
    cudaGetSymbolAddress((void**)&cH, g_cH);    cudaGetSymbolAddress((void**)&cL, g_cL);
    cudaGetSymbolAddress((void**)&ev, g_evict);

    cudaFuncSetAttribute((const void*)gemm_mma<256,256,true,false,false,false>,
                         cudaFuncAttributeMaxDynamicSharedMemorySize, GSMEM_TOTAL);
    cudaFuncSetAttribute((const void*)gemm_mma<256,256,false,true,false,false>,
                         cudaFuncAttributeMaxDynamicSharedMemorySize, GSMEM_TOTAL);
    cudaFuncSetAttribute((const void*)gemm_mma<256,128,true,false,true,true>,
                         cudaFuncAttributeMaxDynamicSharedMemorySize, GSMEM_TOTAL);

    const float qk_scale = 0.08838834764831845f;  // 1/sqrt(128)
    const int splitBlocks = NELT/8/256;

    // 0) tables + evict/progress init
    rope_tables<<<(Sc*64)/256, 256>>>();

    // 1) bf16 hi/lo splits
    split_plain<<<splitBlocks, 256>>>(hs, hsH, hsL, NELT);
    split_w4<<<dim3(splitBlocks,4), 256>>>(wq, wk, wv, wo, wH, wL);

    // 2) Fused QKV projections
    gemm_mma<256,256,true,false,false,false><<<dim3(8,16,3), 256, GSMEM_TOTAL>>>(
        hsH, hsL, wH, wL, lin, nullptr, nullptr, HIDc, HIDc, HIDc,
        0, (long long)HIDc*HIDc, (long long)NELT, 0, 1, 1.f);

    // 3) RoPE + layout + split
    rope_split<<<NELT/256, 256>>>();

    // 4) QK^T causal, scaled
    gemm_mma<256,256,false,true,false,false><<<dim3(4,8,ZB), 256, GSMEM_TOTAL>>>(
        QH, QL, KH, KL, P, nullptr, nullptr, HDc, HDc, Sc,
        (long long)Sc*HDc, (long long)Sc*HDc,
        (long long)Sc*Sc, 0, 1, qk_scale);

    // 5) softmax
    softmax_causal<<<ZB*Sc, 256>>>(P);

    // 6) FAT: scan + head maskrenorm + hardened progress-gated tail maskrenorm
    scan_fat<<<ZB + ZB*HEADROWS + ZB*TAILROWS, 128>>>(P, ev, PH, PL);

    // 7) PV -> ctx
    gemm_mma<256,128,true,false,true,true><<<dim3(1,8,ZB), 256, GSMEM_TOTAL>>>(
        PH, PL, VH, VL, nullptr, cH, cL, Sc, HDc, HIDc,
        (long long)Sc*Sc, (long long)Sc*HDc,
        (long long)Sc*HIDc, (long long)HDc, NHc, 1.f);

    // 8) output projection
    gemm_mma<256,256,true,false,false,false><<<dim3(8,16,1), 256, GSMEM_TOTAL>>>(
        cH, cL, wH + 3*(size_t)HIDc*HIDc, wL + 3*(size_t)HIDc*HIDc, out,
        nullptr, nullptr, HIDc, HIDc, HIDc, 0, 0, 0, 0, 1, 1.f);
}

// round 17
// speedup vs baseline: 1.1482x; 1.1390x over previous
#include <cuda_runtime.h>
#include <cuda_bf16.h>
#include <math.h>
#include <float.h>
#include <stdint.h>

// Problem constants
#define Bc    2
#define Sc    1024
#define HIDc  2048
#define NHc   16
#define HDc   128
#define SBc   20
#define RBc   82
#define CBc   163
#define FFc   0.9f
#define BSc   (Bc*Sc)          // 2048
#define ZB    (Bc*NHc)         // 32
#define NELT  (BSc*HIDc)       // 4M
#define HEADROWS (CBc+1)       // 164 rows with no evict dependency
#define TAILROWS (Sc-HEADROWS) // 860

// ----------------------------------------------------------------------------
// Scratch
// ----------------------------------------------------------------------------
__device__ __align__(1024) float g_lin[3*NELT];
__device__ __align__(1024) __nv_bfloat16 g_hsH[NELT];
__device__ __align__(1024) __nv_bfloat16 g_hsL[NELT];
__device__ __align__(1024) __nv_bfloat16 g_wH[4*HIDc*HIDc];
__device__ __align__(1024) __nv_bfloat16 g_wL[4*HIDc*HIDc];
__device__ __align__(1024) __nv_bfloat16 g_QH[ZB*Sc*HDc];
__device__ __align__(1024) __nv_bfloat16 g_QL[ZB*Sc*HDc];
__device__ __align__(1024) __nv_bfloat16 g_KH[ZB*Sc*HDc];
__device__ __align__(1024) __nv_bfloat16 g_KL[ZB*Sc*HDc];
__device__ __align__(1024) __nv_bfloat16 g_VH[ZB*Sc*HDc];
__device__ __align__(1024) __nv_bfloat16 g_VL[ZB*Sc*HDc];
__device__ __align__(1024) float g_P[(size_t)ZB*Sc*Sc];
__device__ __align__(1024) __nv_bfloat16 g_PH[(size_t)ZB*Sc*Sc];
__device__ __align__(1024) __nv_bfloat16 g_PL[(size_t)ZB*Sc*Sc];
__device__ __align__(1024) __nv_bfloat16 g_cH[NELT];
__device__ __align__(1024) __nv_bfloat16 g_cL[NELT];
__device__ int g_evict[ZB*Sc];
__device__ float g_tcos[Sc*64];
__device__ float g_tsin[Sc*64];
__device__ float g_wcoef[CBc];

// Packed causal grid LUT for QK^T (NT=256): 20 valid (nx,my) pairs
__constant__ int c_qknx[20] = {0, 0, 0,1, 0,1, 0,1,2, 0,1,2, 0,1,2,3, 0,1,2,3};
__constant__ int c_qkmy[20] = {0, 1, 2,2, 3,3, 4,4,4, 5,5,5, 6,6,6,6, 7,7,7,7};

// ----------------------------------------------------------------------------
// PTX helpers
// ----------------------------------------------------------------------------
__device__ __forceinline__ uint32_t smem_u32(const void* p){
    uint32_t a;
    asm("{ .reg .u64 t; cvta.to.shared.u64 t, %1; cvt.u32.u64 %0, t; }":"=r"(a):"l"(p));
    return a;
}
__device__ __forceinline__ void cp16(uint32_t d, const void* s){
    asm volatile("cp.async.cg.shared.global [%0], [%1], 16;"::"r"(d),"l"(s));
}
#define CP_COMMIT() asm volatile("cp.async.commit_group;":::"memory")
#define CP_WAIT(n)  asm volatile("cp.async.wait_group %0;"::"n"(n):"memory")

__device__ __forceinline__ void ldsm4(uint32_t r[4], uint32_t a){
    asm volatile("ldmatrix.sync.aligned.m8n8.x4.shared.b16 {%0,%1,%2,%3}, [%4];"
        : "=r"(r[0]),"=r"(r[1]),"=r"(r[2]),"=r"(r[3]) : "r"(a));
}
__device__ __forceinline__ void ldsm4t(uint32_t r[4], uint32_t a){
    asm volatile("ldmatrix.sync.aligned.m8n8.x4.trans.shared.b16 {%0,%1,%2,%3}, [%4];"
        : "=r"(r[0]),"=r"(r[1]),"=r"(r[2]),"=r"(r[3]) : "r"(a));
}
__device__ __forceinline__ void mma16816(float d[4], const uint32_t a[4], const uint32_t b[2]){
    asm volatile("mma.sync.aligned.m16n8k16.row.col.f32.bf16.bf16.f32 "
        "{%0,%1,%2,%3},{%4,%5,%6,%7},{%8,%9},{%0,%1,%2,%3};"
        : "+f"(d[0]),"+f"(d[1]),"+f"(d[2]),"+f"(d[3])
        : "r"(a[0]),"r"(a[1]),"r"(a[2]),"r"(a[3]),"r"(b[0]),"r"(b[1]));
}

#define GSMEM_TOTAL 196608   // 192 KB

template<int NROWS, int NTH>
__device__ __forceinline__ void copy_rk(uint32_t dst, const __nv_bfloat16* src,
                                        int ld, int tid){
#pragma unroll
    for (int i=0;i<NROWS*8/NTH;i++){
        int idx = tid + i*NTH;
        int r = idx>>3, c = idx&7;
        uint32_t sw = (uint32_t)(r*128) + (uint32_t)(((c ^ (r&7))<<4));
        cp16(dst + sw, (const char*)src + ((long long)r*ld + c*8)*2);
    }
}
template<int NCOLS, int NTH>
__device__ __forceinline__ void copy_kn(uint32_t dst, const __nv_bfloat16* src,
                                        int ld, int tid){
    const int CPR = NCOLS/8;
#pragma unroll
    for (int i=0;i<64*CPR/NTH;i++){
        int idx = tid + i*NTH;
        int r = idx/CPR, c = idx%CPR;
        uint32_t sw = (uint32_t)(r*(NCOLS*2)) + (uint32_t)(((c ^ (r&7))<<4));
        cp16(dst + sw, (const char*)src + ((long long)r*ld + c*8)*2);
    }
}

// ----------------------------------------------------------------------------
// HMMA GEMM (R9-proven); PACKED: blockIdx.x indexes causal (nx,my) LUT
// ----------------------------------------------------------------------------
template<int NTH, int NT, bool BKN, bool CAUSAL, bool SPLITOUT, bool KTRUNC, bool PACKED>
__global__ void __launch_bounds__(NTH) gemm_mma(
    const __nv_bfloat16* __restrict__ Ah, const __nv_bfloat16* __restrict__ Al,
    const __nv_bfloat16* __restrict__ Bh, const __nv_bfloat16* __restrict__ Bl,
    float* __restrict__ C,
    __nv_bfloat16* __restrict__ CH, __nv_bfloat16* __restrict__ CL,
    int K, int ldb, int ldc,
    long long sA, long long sB, long long sCo, long long sCi, int ndiv, float alpha)
{
    int my, n0;
    if (PACKED){
        my = c_qkmy[blockIdx.x];
        n0 = c_qknx[blockIdx.x]*NT;
    } else {
        my = KTRUNC ? (gridDim.y - 1 - blockIdx.y) : blockIdx.y;
        n0 = blockIdx.x*NT;
    }
    const int m0 = my*128, z = blockIdx.z;
    if (CAUSAL && !PACKED && n0 > m0 + 127) return;
    const int NN8 = NT/32;
    const int NHALF = NN8/4;
    const int MWT = (NTH==512) ? 32 : 64;
    const int MB  = MWT/16;
    const int TILEA = 16384;
    const int TILEBB = NT*128;
    const int STG = 2*TILEA + 2*TILEBB;
    const int NS = (NT==256) ? 2 : 3;

    extern __shared__ __align__(1024) char smem[];
    const uint32_t sb = smem_u32(smem);
    Ah += (long long)z*sA; Al += (long long)z*sA;
    Bh += (long long)z*sB; Bl += (long long)z*sB;
    long long coff = (long long)(z/ndiv)*sCo + (long long)(z%ndiv)*sCi;
    if (SPLITOUT){ CH += coff; CL += coff; } else { C += coff; }

    const int tid = threadIdx.x, lane = tid&31, wid = tid>>5;
    const int wm = wid>>2, wn = wid&3;

    float acc[MB][NN8][4];
#pragma unroll
    for (int a=0;a<MB;a++)
#pragma unroll
        for (int b=0;b<NN8;b++)
#pragma unroll
            for (int c=0;c<4;c++) acc[a][b][c] = 0.f;

    const int nch = KTRUNC ? ((m0+128)>>6) : (K>>6);

#define LOAD_CHUNK(cc, ss) do{ \
    uint32_t bbase = sb + (uint32_t)(ss)*STG; \
    copy_rk<128,NTH>(bbase,         Ah + (long long)m0*K + (cc)*64, K, tid); \
    copy_rk<128,NTH>(bbase + TILEA, Al + (long long)m0*K + (cc)*64, K, tid); \
    if (BKN){ \
        copy_kn<NT,NTH>(bbase + 2*TILEA,          Bh + (long long)(cc)*64*ldb + n0, ldb, tid); \
        copy_kn<NT,NTH>(bbase + 2*TILEA + TILEBB, Bl + (long long)(cc)*64*ldb + n0, ldb, tid); \
    } else { \
        copy_rk<NT,NTH>(bbase + 2*TILEA,          Bh + (long long)n0*K + (cc)*64, K, tid); \
        copy_rk<NT,NTH>(bbase + 2*TILEA + TILEBB, Bl + (long long)n0*K + (cc)*64, K, tid); \
    } \
    CP_COMMIT(); }while(0)

    LOAD_CHUNK(0, 0);
    if (NS > 1 && nch > 1) LOAD_CHUNK(1, 1);
    if (NS > 2 && nch > 2) LOAD_CHUNK(2, 2);

    const uint32_t axor = (uint32_t)(lane&7);

    for (int c=0; c<nch; c++){
        int pend = nch-1-c; if (pend > NS-1) pend = NS-1;
        if (pend >= 2) CP_WAIT(2);
        else if (pend == 1) CP_WAIT(1);
        else CP_WAIT(0);
        __syncthreads();
        uint32_t base = sb + (uint32_t)(c % NS)*STG;
#pragma unroll
        for (int ks=0; ks<4; ks++){
#pragma unroll
            for (int half=0; half<NHALF; half++){
                uint32_t bh[4][2], bl[4][2];
#pragma unroll
                for (int nb=0;nb<2;nb++){
                    uint32_t t[4];
                    int gg = half*2 + nb;
                    if (BKN){
                        uint32_t row = (uint32_t)(ks*16 + (lane&7) + (((lane>>3)&1)<<3));
                        uint32_t ch  = ((uint32_t)(wn*NN8 + gg*2 + (lane>>4)) ^ axor);
                        uint32_t ad  = base + 2*TILEA + row*(NT*2) + (ch<<4);
                        ldsm4t(t, ad);
                        bh[2*nb][0]=t[0]; bh[2*nb][1]=t[1]; bh[2*nb+1][0]=t[2]; bh[2*nb+1][1]=t[3];
                        ldsm4t(t, ad + TILEBB);
                        bl[2*nb][0]=t[0]; bl[2*nb][1]=t[1]; bl[2*nb+1][0]=t[2]; bl[2*nb+1][1]=t[3];
                    } else {
                        uint32_t row = (uint32_t)(wn*(NT/4) + gg*16 + (lane&7) + ((lane>>4)<<3));
                        uint32_t ch  = ((uint32_t)(ks*2 + ((lane>>3)&1)) ^ axor);
                        uint32_t ad  = base + 2*TILEA + row*128 + (ch<<4);
                        ldsm4(t, ad);
                        bh[2*nb][0]=t[0]; bh[2*nb][1]=t[1]; bh[2*nb+1][0]=t[2]; bh[2*nb+1][1]=t[3];
                        ldsm4(t, ad + TILEBB);
                        bl[2*nb][0]=t[0]; bl[2*nb][1]=t[1]; bl[2*nb+1][0]=t[2]; bl[2*nb+1][1]=t[3];
                    }
                }
#pragma unroll
                for (int mb=0;mb<MB;mb++){
                    uint32_t ah[4], al[4];
                    uint32_t row = (uint32_t)(wm*MWT + mb*16 + (lane&15));
                    uint32_t col = (((uint32_t)(ks*2 + (lane>>4)) ^ (row&7u))<<4);
                    uint32_t ad = base + row*128 + col;
                    ldsm4(ah, ad);
                    ldsm4(al, ad + TILEA);
#pragma unroll
                    for (int n8=0;n8<4;n8++){
                        int g8 = half*4 + n8;
                        mma16816(acc[mb][g8], ah, bh[n8]);
                        mma16816(acc[mb][g8], ah, bl[n8]);
                        mma16816(acc[mb][g8], al, bh[n8]);
                    }
                }
            }
        }
        __syncthreads();
        if (c + NS < nch) LOAD_CHUNK(c + NS, c % NS);
    }
#undef LOAD_CHUNK

#pragma unroll
    for (int mb=0;mb<MB;mb++){
        int r0 = m0 + wm*MWT + mb*16 + (lane>>2);
#pragma unroll
        for (int n8=0;n8<NN8;n8++){
            int cc = n0 + wn*(NT/4) + n8*8 + (lane&3)*2;
            float vx0 = acc[mb][n8][0]*alpha, vy0 = acc[mb][n8][1]*alpha;
            float vx1 = acc[mb][n8][2]*alpha, vy1 = acc[mb][n8][3]*alpha;
            if (SPLITOUT){
                __nv_bfloat162 h0, l0, h1, l1;
                h0.x = __float2bfloat16(vx0); h0.y = __float2bfloat16(vy0);
                l0.x = __float2bfloat16(vx0 - __bfloat162float(h0.x));
                l0.y = __float2bfloat16(vy0 - __bfloat162float(h0.y));
                h1.x = __float2bfloat16(vx1); h1.y = __float2bfloat16(vy1);
                l1.x = __float2bfloat16(vx1 - __bfloat162float(h1.x));
                l1.y = __float2bfloat16(vy1 - __bfloat162float(h1.y));
                *(__nv_bfloat162*)&CH[(long long)r0*ldc + cc] = h0;
                *(__nv_bfloat162*)&CL[(long long)r0*ldc + cc] = l0;
                *(__nv_bfloat162*)&CH[(long long)(r0+8)*ldc + cc] = h1;
                *(__nv_bfloat162*)&CL[(long long)(r0+8)*ldc + cc] = l1;
            } else {
                float2 v0; v0.x = vx0; v0.y = vy0;
                float2 v1; v1.x = vx1; v1.y = vy1;
                *(float2*)&C[(long long)r0*ldc + cc] = v0;
                *(float2*)&C[(long long)(r0+8)*ldc + cc] = v1;
            }
        }
    }
}

// ----------------------------------------------------------------------------
// fp32 -> bf16 hi/lo split; fused single launch (grid.y: 0=hs, 1..4=weights)
// ----------------------------------------------------------------------------
__device__ __forceinline__ void split_body(const float* __restrict__ X,
                                           __nv_bfloat16* __restrict__ H,
                                           __nv_bfloat16* __restrict__ L, int i)
{
    float4 v = *(const float4*)&X[i];
    float4 w = *(const float4*)&X[i+4];
    __nv_bfloat16 h0=__float2bfloat16(v.x), h1=__float2bfloat16(v.y);
    __nv_bfloat16 h2=__float2bfloat16(v.z), h3=__float2bfloat16(v.w);
    __nv_bfloat16 h4=__float2bfloat16(w.x), h5=__float2bfloat16(w.y);
    __nv_bfloat16 h6=__float2bfloat16(w.z), h7=__float2bfloat16(w.w);
    __nv_bfloat162 H01{h0,h1}, H23{h2,h3}, H45{h4,h5}, H67{h6,h7};
    *(__nv_bfloat162*)&H[i]   = H01; *(__nv_bfloat162*)&H[i+2] = H23;
    *(__nv_bfloat162*)&H[i+4] = H45; *(__nv_bfloat162*)&H[i+6] = H67;
    __nv_bfloat162 L01, L23, L45, L67;
    L01.x = __float2bfloat16(v.x - __bfloat162float(h0));
    L01.y = __float2bfloat16(v.y - __bfloat162float(h1));
    L23.x = __float2bfloat16(v.z - __bfloat162float(h2));
    L23.y = __float2bfloat16(v.w - __bfloat162float(h3));
    L45.x = __float2bfloat16(w.x - __bfloat162float(h4));
    L45.y = __float2bfloat16(w.y - __bfloat162float(h5));
    L67.x = __float2bfloat16(w.z - __bfloat162float(h6));
    L67.y = __float2bfloat16(w.w - __bfloat162float(h7));
    *(__nv_bfloat162*)&L[i]   = L01; *(__nv_bfloat162*)&L[i+2] = L23;
    *(__nv_bfloat162*)&L[i+4] = L45; *(__nv_bfloat162*)&L[i+6] = L67;
}

__global__ void split_all(const float* __restrict__ hs,
                          const float* __restrict__ w0, const float* __restrict__ w1,
                          const float* __restrict__ w2, const float* __restrict__ w3,
                          __nv_bfloat16* __restrict__ hsH, __nv_bfloat16* __restrict__ hsL,
                          __nv_bfloat16* __restrict__ wH,  __nv_bfloat16* __restrict__ wL)
{
    int i = (blockIdx.x*blockDim.x + threadIdx.x)*8;
    int sel = blockIdx.y;
    if (sel == 0){
        split_body(hs, hsH, hsL, i);
    } else {
        const float* src = (sel==1)?w0:(sel==2)?w1:(sel==3)?w2:w3;
        size_t off = (size_t)(sel-1) * HIDc * HIDc;
        split_body(src, wH + off, wL + off, i);
    }
}

// ----------------------------------------------------------------------------
// Tables
// ----------------------------------------------------------------------------
__global__ void rope_tables()
{
    int idx = blockIdx.x*blockDim.x + threadIdx.x;
    int s = idx >> 6, i = idx & 63;
    double inv = pow(10000.0, -(double)i/64.0);
    double a = (double)s * inv;
    g_tcos[idx] = (float)cos(a);
    g_tsin[idx] = (float)sin(a);
    if (idx < CBc) g_wcoef[idx] = (float)pow((double)FFc, (double)(CBc-1-idx));
}

// ----------------------------------------------------------------------------
// RoPE + layout + split
// ----------------------------------------------------------------------------
__global__ void rope_split()
{
    long long idx = (long long)blockIdx.x * blockDim.x + threadIdx.x;
    if (idx >= (long long)NELT) return;

    int d = (int)(idx % HDc);
    int h = (int)((idx / HDc) % NHc);
    int s = (int)((idx / HIDc) % Sc);
    int b = (int)(idx / ((long long)Sc * HIDc));
    int z = b*NHc + h;

    long long lin = (long long)(b * Sc + s) * HIDc + h * HDc + d;
    long long out = (long long)(z * Sc + s) * HDc + d;

    const float* Qlin = g_lin;
    const float* Klin = g_lin + NELT;
    const float* Vlin = g_lin + 2*(long long)NELT;

    float q = Qlin[lin];
    float k = Klin[lin];
    float qr, kr;
    if (d < 64) { qr = -Qlin[lin + 64]; kr = -Klin[lin + 64]; }
    else        { qr =  Qlin[lin - 64]; kr =  Klin[lin - 64]; }

    int ti = (s<<6) + (d & 63);
    float c = g_tcos[ti], sn = g_tsin[ti];

    float qv = q * c + qr * sn;
    float kv = k * c + kr * sn;

    __nv_bfloat16 qh = __float2bfloat16(qv);
    g_QH[out] = qh; g_QL[out] = __float2bfloat16(qv - __bfloat162float(qh));
    __nv_bfloat16 kh = __float2bfloat16(kv);
    g_KH[out] = kh; g_KL[out] = __float2bfloat16(kv - __bfloat162float(kh));

    float vv = Vlin[lin];
    __nv_bfloat16 vh = __float2bfloat16(vv);
    g_VH[out] = vh; g_VL[out] = __float2bfloat16(vv - __bfloat162float(vh));
}

// ----------------------------------------------------------------------------
// Causal row softmax (R9)
// ----------------------------------------------------------------------------
__global__ void __launch_bounds__(256) softmax_causal(float* __restrict__ P)
{
    __shared__ float smA[9];
    __shared__ float smB[9];
    long long row = blockIdx.x;
    int r = (int)(row & (Sc-1));
    float* p = P + row * Sc;
    const int tid = threadIdx.x;
    const int lane = tid & 31, wid = tid >> 5;

    float v[4];
    float mx = -FLT_MAX;
#pragma unroll
    for (int i = 0; i < 4; i++) {
        int jj = tid + i*256;
        v[i] = (jj <= r) ? p[jj] : -FLT_MAX;
        mx = fmaxf(mx, v[i]);
    }
#pragma unroll
    for (int o = 16; o; o >>= 1) mx = fmaxf(mx, __shfl_xor_sync(0xffffffffu, mx, o));
    if (lane == 0) smA[wid] = mx;
    __syncthreads();
    if (tid < 8) {
        float x = smA[tid];
#pragma unroll
        for (int o = 4; o; o >>= 1) x = fmaxf(x, __shfl_xor_sync(0xffu, x, o));
        if (tid == 0) smA[8] = x;
    }
    __syncthreads();
    mx = smA[8];

    float sum = 0.f;
#pragma unroll
    for (int i = 0; i < 4; i++) { v[i] = expf(v[i] - mx); sum += v[i]; }
#pragma unroll
    for (int o = 16; o; o >>= 1) sum += __shfl_xor_sync(0xffffffffu, sum, o);
    if (lane == 0) smB[wid] = sum;
    __syncthreads();
    if (tid < 8) {
        float x = smB[tid];
#pragma unroll
        for (int o = 4; o; o >>= 1) x += __shfl_xor_sync(0xffu, x, o);
        if (tid == 0) smB[8] = x;
    }
    __syncthreads();
    sum = smB[8];

    float inv = 1.f / sum;
#pragma unroll
    for (int i = 0; i < 4; i++) p[tid + i * 256] = v[i] * inv;
}

// ----------------------------------------------------------------------------
// FAT kernel (R13-winning): blocks [0,ZB) = scan (redux argmin, batch evict
// write); blocks >= ZB = head maskrenorm (r <= CB) overlapped in scan shadow.
// ----------------------------------------------------------------------------
__global__ void __launch_bounds__(128) scan_fat(const float* __restrict__ P,
                                               int* __restrict__ evict,
                                               __nv_bfloat16* __restrict__ PH,
                                               __nv_bfloat16* __restrict__ PL)
{
    const int tid = threadIdx.x;
    const int lane = tid & 31, wid = tid >> 5;

    if (blockIdx.x >= ZB){
        // ---- HEAD maskrenorm: row r <= CB, keep = all ----
        __shared__ float hs[4];
        int bi = blockIdx.x - ZB;
        int z = bi / HEADROWS;
        long long row = (long long)z * Sc + (bi % HEADROWS);
        const float* p = P + row * Sc;
        int j0 = tid * 8;
        float v[8];
        float4 a = *(const float4*)&p[j0];
        float4 b = *(const float4*)&p[j0+4];
        v[0]=a.x;v[1]=a.y;v[2]=a.z;v[3]=a.w;v[4]=b.x;v[5]=b.y;v[6]=b.z;v[7]=b.w;
        float sum = 0.f;
#pragma unroll
        for (int k=0;k<8;k++) sum += v[k];
#pragma unroll
        for (int o=16;o;o>>=1) sum += __shfl_xor_sync(0xffffffffu, sum, o);
        if (lane == 0) hs[wid] = sum;
        __syncthreads();
        float total = hs[0]+hs[1]+hs[2]+hs[3];
        float inv = 1.f / total;
        long long base = row * Sc;
        __nv_bfloat162 H[4], L[4];
#pragma unroll
        for (int k=0;k<4;k++){
            float x = v[2*k]*inv, y = v[2*k+1]*inv;
            H[k].x = __float2bfloat16(x); H[k].y = __float2bfloat16(y);
            L[k].x = __float2bfloat16(x - __bfloat162float(H[k].x));
            L[k].y = __float2bfloat16(y - __bfloat162float(H[k].y));
        }
#pragma unroll
        for (int k=0;k<4;k++){
            *(__nv_bfloat162*)&PH[base + j0 + 2*k] = H[k];
            *(__nv_bfloat162*)&PL[base + j0 + 2*k] = L[k];
        }
        return;
    }

    // ---- scan (R13-winning structure; warp argmin via redux) ----
    const int z = blockIdx.x;
    const float* Pz = P + (long long)z * Sc * Sc;
    const int j0 = tid * 8;
    const float INFV = __int_as_float(0x7f800000);

    __shared__ uint4 part[2][4];
    __shared__ float swc[CBc];

    for (int i = tid; i < CBc; i += 128) swc[i] = g_wcoef[i];
    __syncthreads();

    float sel[8];
#pragma unroll
    for (int k=0;k<8;k++) sel[k] = 0.f;
#pragma unroll 4
    for (int i = 0; i < CBc; i++){
        float w = swc[i];
        float4 a = *(const float4*)&Pz[(long long)i*Sc + j0];
        float4 b = *(const float4*)&Pz[(long long)i*Sc + j0 + 4];
        sel[0] += w*a.x; sel[1] += w*a.y; sel[2] += w*a.z; sel[3] += w*a.w;
        sel[4] += w*b.x; sel[5] += w*b.y; sel[6] += w*b.z; sel[7] += w*b.w;
    }

    int e[8];
#pragma unroll
    for (int k=0;k<8;k++) e[k] = 0x7fffffff;

    float scur[8], snxt[8], sfar[8];
    {
        float4 a, b;
        a = *(const float4*)&Pz[(long long)CBc*Sc + j0];
        b = *(const float4*)&Pz[(long long)CBc*Sc + j0 + 4];
        scur[0]=a.x;scur[1]=a.y;scur[2]=a.z;scur[3]=a.w;
        scur[4]=b.x;scur[5]=b.y;scur[6]=b.z;scur[7]=b.w;
        a = *(const float4*)&Pz[(long long)(CBc+1)*Sc + j0];
        b = *(const float4*)&Pz[(long long)(CBc+1)*Sc + j0 + 4];
        snxt[0]=a.x;snxt[1]=a.y;snxt[2]=a.z;snxt[3]=a.w;
        snxt[4]=b.x;snxt[5]=b.y;snxt[6]=b.z;snxt[7]=b.w;
        a = *(const float4*)&Pz[(long long)(CBc+2)*Sc + j0];
        b = *(const float4*)&Pz[(long long)(CBc+2)*Sc + j0 + 4];
        sfar[0]=a.x;sfar[1]=a.y;sfar[2]=a.z;sfar[3]=a.w;
        sfar[4]=b.x;sfar[5]=b.y;sfar[6]=b.z;sfar[7]=b.w;
    }

    float total;
    {
        float ps = 0.f;
#pragma unroll
        for (int k=0;k<8;k++) ps += scur[k];
#pragma unroll
        for (int o=16;o;o>>=1) ps += __shfl_xor_sync(0xffffffffu, ps, o);
        if (lane == 0) part[0][wid] = make_uint4(0u,0u,0u,__float_as_uint(ps));
        __syncthreads();
        total = 0.f;
#pragma unroll
        for (int w=0;w<4;w++) total += __uint_as_float(part[0][w].w);
    }

    for (int t = CBc; t <= Sc - 2; t++){
        const int par = t & 1;
        const float inv = 1.f / total;

#pragma unroll
        for (int k=0;k<8;k++){
            bool alive = (sel[k] < INFV);
            sel[k] = alive ? (FFc*sel[k] + scur[k]*inv) : INFV;
        }

        const int hi = t - RBc;
        unsigned long long key = ~0ull;
        float scn = 0.f;
#pragma unroll
        for (int k=0;k<8;k++){
            int j = j0 + k;
            if (j >= SBc && j <= hi){
                unsigned long long kk =
                    (((unsigned long long)__float_as_uint(sel[k])) << 32) | (unsigned)j;
                if (kk < key){ key = kk; scn = snxt[k]; }
            }
        }
        float ps = 0.f;
#pragma unroll
        for (int k=0;k<8;k++) if (sel[k] < INFV) ps += snxt[k];

        uint32_t sb32 = (uint32_t)(key>>32);
        uint32_t jpart = (uint32_t)key;
        uint32_t mn = __reduce_min_sync(0xffffffffu, sb32);
        uint32_t jc = (sb32==mn) ? jpart : 0xffffffffu;
        uint32_t jm = __reduce_min_sync(0xffffffffu, jc);
        uint32_t bal = __ballot_sync(0xffffffffu, (sb32==mn) && (jpart==jm));
        int src = __ffs(bal)-1;
        float wscn = __shfl_sync(0xffffffffu, scn, src);
#pragma unroll
        for (int o=16;o;o>>=1) ps += __shfl_xor_sync(0xffffffffu, ps, o);

        if (lane == 0)
            part[par][wid] = make_uint4(jm, mn,
                                        __float_as_uint(wscn), __float_as_uint(ps));
        __syncthreads();

        unsigned long long bk = ~0ull;
        float bscn = 0.f, raw = 0.f;
#pragma unroll
        for (int w=0;w<4;w++){
            uint4 q = part[par][w];
            unsigned long long k2 = (((unsigned long long)q.y)<<32) | q.x;
            if (k2 < bk){ bk = k2; bscn = __uint_as_float(q.z); }
            raw += __uint_as_float(q.w);
        }
        int mi = (int)(bk & 0xffffffffu);

        if (mi >= j0 && mi < j0 + 8){
            sel[mi - j0] = INFV;
            e[mi - j0] = t;
        }
        total = raw - bscn;

#pragma unroll
        for (int k=0;k<8;k++){ scur[k] = snxt[k]; snxt[k] = sfar[k]; }
        if (t + 3 <= Sc - 1){
            float4 a = *(const float4*)&Pz[(long long)(t+3)*Sc + j0];
            float4 b = *(const float4*)&Pz[(long long)(t+3)*Sc + j0 + 4];
            sfar[0]=a.x;sfar[1]=a.y;sfar[2]=a.z;sfar[3]=a.w;
            sfar[4]=b.x;sfar[5]=b.y;sfar[6]=b.z;sfar[7]=b.w;
        }
    }

#pragma unroll
    for (int k=0;k<8;k++) evict[z*Sc + j0 + k] = e[k];
}

// ----------------------------------------------------------------------------
// Keep-mask + renormalize, TAIL rows only (r > CB); R13 semantics.
// ----------------------------------------------------------------------------
__global__ void __launch_bounds__(256) maskrenorm_tail(const float* __restrict__ P,
                                                       const int* __restrict__ evict,
                                                       __nv_bfloat16* __restrict__ PH,
                                                       __nv_bfloat16* __restrict__ PL)
{
    __shared__ float smB[9];
    int bi = blockIdx.x;
    int z = bi / TAILROWS;
    int r = HEADROWS + bi % TAILROWS;
    long long row = (long long)z * Sc + r;
    const float* p = P + row * Sc;
    const int* e = evict + z * Sc;
    const int tid = threadIdx.x;
    const int lane = tid & 31, wid = tid >> 5;

    float v[4];
    float sum = 0.f;
#pragma unroll
    for (int i = 0; i < 4; i++) {
        int jj = tid + i * 256;
        bool keep = (e[jj] >= r);          // r > CBc here
        v[i] = keep ? p[jj] : 0.f;
        sum += v[i];
    }
#pragma unroll
    for (int o = 16; o; o >>= 1) sum += __shfl_xor_sync(0xffffffffu, sum, o);
    if (lane == 0) smB[wid] = sum;
    __syncthreads();
    if (tid < 8) {
        float x = smB[tid];
#pragma unroll
        for (int o = 4; o; o >>= 1) x += __shfl_xor_sync(0xffu, x, o);
        if (tid == 0) smB[8] = x;
    }
    __syncthreads();
    sum = smB[8];

    float inv = 1.f / sum;
    long long base = row * Sc;
#pragma unroll
    for (int i = 0; i < 4; i++) {
        int jj = tid + i * 256;
        float val = v[i] * inv;
        __nv_bfloat16 h = __float2bfloat16(val);
        PH[base + jj] = h;
        PL[base + jj] = __float2bfloat16(val - __bfloat162float(h));
    }
}

// ----------------------------------------------------------------------------
// Launch
// ----------------------------------------------------------------------------
extern "C" void kernel_launch(void* const* d_in, const int* in_sizes, int n_in,
                              void* d_out, int out_size)
{
    (void)in_sizes; (void)n_in; (void)out_size;
    const float* hs = (const float*)d_in[0];
    const float* wq = (const float*)d_in[1];
    const float* wk = (const float*)d_in[2];
    const float* wv = (const float*)d_in[3];
    const float* wo = (const float*)d_in[4];
    float* out = (float*)d_out;

    float *lin, *P;
    __nv_bfloat16 *hsH, *hsL, *wH, *wL;
    __nv_bfloat16 *QH, *QL, *KH, *KL, *VH, *VL, *PH, *PL, *cH, *cL;
    int* ev;
    cudaGetSymbolAddress((void**)&lin, g_lin);
    cudaGetSymbolAddress((void**)&hsH, g_hsH);  cudaGetSymbolAddress((void**)&hsL, g_hsL);
    cudaGetSymbolAddress((void**)&wH, g_wH);    cudaGetSymbolAddress((void**)&wL, g_wL);
    cudaGetSymbolAddress((void**)&QH, g_QH);    cudaGetSymbolAddress((void**)&QL, g_QL);
    cudaGetSymbolAddress((void**)&KH, g_KH);    cudaGetSymbolAddress((void**)&KL, g_KL);
    cudaGetSymbolAddress((void**)&VH, g_VH);    cudaGetSymbolAddress((void**)&VL, g_VL);
    cudaGetSymbolAddress((void**)&P, g_P);
    cudaGetSymbolAddress((void**)&PH, g_PH);    cudaGetSymbolAddress((void**)&PL, g_PL);
    cudaGetSymbolAddress((void**)&cH, g_cH);    cudaGetSymbolAddress((void**)&cL, g_cL);
    cudaGetSymbolAddress((void**)&ev, g_evict);

    cudaFuncSetAttribute((const void*)gemm_mma<256,256,true,false,false,false,false>,
                         cudaFuncAttributeMaxDynamicSharedMemorySize, GSMEM_TOTAL);
    cudaFuncSetAttribute((const void*)gemm_mma<256,256,false,true,false,false,true>,
                         cudaFuncAttributeMaxDynamicSharedMemorySize, GSMEM_TOTAL);
    cudaFuncSetAttribute((const void*)gemm_mma<256,128,true,false,true,true,false>,
                         cudaFuncAttributeMaxDynamicSharedMemorySize, GSMEM_TOTAL);

    const float qk_scale = 0.08838834764831845f;  // 1/sqrt(128)
    const int splitBlocks = NELT/8/256;

    // 0) tables
    rope_tables<<<(Sc*64)/256, 256>>>();

    // 1) bf16 hi/lo splits: hs + 4 weights in ONE launch
    split_all<<<dim3(splitBlocks,5), 256>>>(hs, wq, wk, wv, wo, hsH, hsL, wH, wL);

    // 2) Fused QKV projections
    gemm_mma<256,256,true,false,false,false,false><<<dim3(8,16,3), 256, GSMEM_TOTAL>>>(
        hsH, hsL, wH, wL, lin, nullptr, nullptr, HIDc, HIDc, HIDc,
        0, (long long)HIDc*HIDc, (long long)NELT, 0, 1, 1.f);

    // 3) RoPE + layout + split
    rope_split<<<NELT/256, 256>>>();

    // 4) QK^T causal, scaled — packed grid (20 live blocks per z)
    gemm_mma<256,256,false,true,false,false,true><<<dim3(20,1,ZB), 256, GSMEM_TOTAL>>>(
        QH, QL, KH, KL, P, nullptr, nullptr, HDc, HDc, Sc,
        (long long)Sc*HDc, (long long)Sc*HDc,
        (long long)Sc*Sc, 0, 1, qk_scale);

    // 5) softmax
    softmax_causal<<<ZB*Sc, 256>>>(P);

    // 6) FAT: eviction scan + head-row maskrenorm overlapped (R13-winning)
    scan_fat<<<ZB + ZB*HEADROWS, 128>>>(P, ev, PH, PL);

    // 7) tail maskrenorm (rows r > CB)
    maskrenorm_tail<<<ZB*TAILROWS, 256>>>(P, ev, PH, PL);

    // 8) PV -> ctx
    gemm_mma<256,128,true,false,true,true,false><<<dim3(1,8,ZB), 256, GSMEM_TOTAL>>>(
        PH, PL, VH, VL, nullptr, cH, cL, Sc, HDc, HIDc,
        (long long)Sc*Sc, (long long)Sc*HDc,
        (long long)Sc*HIDc, (long long)HDc, NHc, 1.f);

    // 9) output projection
    gemm_mma<256,256,true,false,false,false,false><<<dim3(8,16,1), 256, GSMEM_TOTAL>>>(
        cH, cL, wH + 3*(size_t)HIDc*HIDc, wL + 3*(size_t)HIDc*HIDc, out,
        nullptr, nullptr, HIDc, HIDc, HIDc, 0, 0, 0, 0, 1, 1.f);
}